// round 7
// baseline (speedup 1.0000x reference)
#include <cuda_runtime.h>
#include <cuda_bf16.h>
#include <math.h>
#include <float.h>

// ---------------- problem constants ----------------
#define SEQ  2048
#define BSZ  2
#define EMB  1024
#define NH   16
#define HD   64
#define BH   (BSZ*NH)          // 32
#define MROWS (SEQ*BSZ)        // 4096

// ---------------- scratch (static device arrays) ----------------
__device__ __align__(1024) __nv_bfloat16 s_xq_hi[(size_t)MROWS*EMB];
__device__ __align__(1024) __nv_bfloat16 s_xq_lo[(size_t)MROWS*EMB];
__device__ __align__(1024) __nv_bfloat16 s_xk_hi[(size_t)MROWS*EMB];
__device__ __align__(1024) __nv_bfloat16 s_xk_lo[(size_t)MROWS*EMB];
__device__ __align__(1024) __nv_bfloat16 s_xv_hi[(size_t)MROWS*EMB];
__device__ __align__(1024) __nv_bfloat16 s_xv_lo[(size_t)MROWS*EMB];
__device__ __align__(1024) __nv_bfloat16 s_wq_hi[(size_t)EMB*EMB];
__device__ __align__(1024) __nv_bfloat16 s_wq_lo[(size_t)EMB*EMB];
__device__ __align__(1024) __nv_bfloat16 s_wk_hi[(size_t)EMB*EMB];
__device__ __align__(1024) __nv_bfloat16 s_wk_lo[(size_t)EMB*EMB];
__device__ __align__(1024) __nv_bfloat16 s_wv_hi[(size_t)EMB*EMB];
__device__ __align__(1024) __nv_bfloat16 s_wv_lo[(size_t)EMB*EMB];
__device__ __align__(1024) __nv_bfloat16 s_ow_hi[(size_t)EMB*EMB];
__device__ __align__(1024) __nv_bfloat16 s_ow_lo[(size_t)EMB*EMB];
__device__ __align__(1024) __nv_bfloat16 s_q_hi[(size_t)BH*SEQ*HD];
__device__ __align__(1024) __nv_bfloat16 s_q_lo[(size_t)BH*SEQ*HD];
__device__ __align__(1024) __nv_bfloat16 s_k_hi[(size_t)BH*SEQ*HD];
__device__ __align__(1024) __nv_bfloat16 s_k_lo[(size_t)BH*SEQ*HD];
__device__ __align__(1024) __nv_bfloat16 s_v_hi[(size_t)BH*HD*SEQ];  // [bh][d][s]
__device__ __align__(1024) __nv_bfloat16 s_v_lo[(size_t)BH*HD*SEQ];
__device__ __align__(1024) float         g_attn[(size_t)BH*SEQ*SEQ]; // 512 MB
__device__ __align__(1024) __nv_bfloat16 s_p_hi[(size_t)BH*SEQ*SEQ]; // 256 MB
__device__ __align__(1024) __nv_bfloat16 s_p_lo[(size_t)BH*SEQ*SEQ]; // 256 MB
__device__ __align__(1024) __nv_bfloat16 s_c_hi[(size_t)MROWS*EMB];
__device__ __align__(1024) __nv_bfloat16 s_c_lo[(size_t)MROWS*EMB];

// ---------------- PTX helpers ----------------
__device__ __forceinline__ unsigned smem_u32(const void* p) {
    unsigned a;
    asm("{ .reg .u64 t; cvta.to.shared.u64 t, %1; cvt.u32.u64 %0, t; }"
        : "=r"(a) : "l"(p));
    return a;
}
__device__ __forceinline__ void cpasync16(unsigned dst, const void* src) {
    asm volatile("cp.async.cg.shared.global [%0], [%1], 16;" :: "r"(dst), "l"(src));
}
#define CP_COMMIT() asm volatile("cp.async.commit_group;" ::: "memory")
#define CP_WAIT0()  asm volatile("cp.async.wait_group 0;" ::: "memory")
#define CP_WAIT1()  asm volatile("cp.async.wait_group 1;" ::: "memory")

__device__ __forceinline__ void ldsm4(unsigned r[4], unsigned addr) {
    asm volatile("ldmatrix.sync.aligned.m8n8.x4.shared.b16 {%0,%1,%2,%3}, [%4];"
        : "=r"(r[0]), "=r"(r[1]), "=r"(r[2]), "=r"(r[3]) : "r"(addr));
}
__device__ __forceinline__ void mma_bf16(float* d, const unsigned a[4],
                                         unsigned b0, unsigned b1) {
    asm volatile("mma.sync.aligned.m16n8k16.row.col.f32.bf16.bf16.f32 "
        "{%0,%1,%2,%3}, {%4,%5,%6,%7}, {%8,%9}, {%0,%1,%2,%3};"
        : "+f"(d[0]), "+f"(d[1]), "+f"(d[2]), "+f"(d[3])
        : "r"(a[0]), "r"(a[1]), "r"(a[2]), "r"(a[3]), "r"(b0), "r"(b1));
}
__device__ __forceinline__ void bsplit(float v, __nv_bfloat16& h, __nv_bfloat16& l) {
    h = __float2bfloat16(v);
    l = __float2bfloat16(v - __bfloat162float(h));
}
// swizzled byte offset within a tile of 64B rows (4 x 16B chunks per row)
__device__ __forceinline__ unsigned swz(int row, int chunk) {
    return (unsigned)(row * 64 + ((chunk ^ ((row >> 1) & 3)) << 4));
}

// ---------------- fused conversion kernels ----------------
struct Split6Args {
    const float*   src[6];
    __nv_bfloat16* hi[6];
    __nv_bfloat16* lo[6];
    int            n4[6];
};

__global__ void split6_kernel(Split6Args a)
{
    const int z = blockIdx.y;
    int i = blockIdx.x * blockDim.x + threadIdx.x;
    if (i >= a.n4[z]) return;
    float4 v = ((const float4*)a.src[z])[i];
    __nv_bfloat162 h0, h1, l0, l1;
    bsplit(v.x, h0.x, l0.x); bsplit(v.y, h0.y, l0.y);
    bsplit(v.z, h1.x, l1.x); bsplit(v.w, h1.y, l1.y);
    ((__nv_bfloat162*)a.hi[z])[2*i]   = h0;
    ((__nv_bfloat162*)a.hi[z])[2*i+1] = h1;
    ((__nv_bfloat162*)a.lo[z])[2*i]   = l0;
    ((__nv_bfloat162*)a.lo[z])[2*i+1] = l1;
}

__global__ void ow_split_kernel(const float* __restrict__ mean,
                                const float* __restrict__ lgstd,
                                const float* __restrict__ eps, int n4)
{
    int i = blockIdx.x * blockDim.x + threadIdx.x;
    if (i >= n4) return;
    float4 m = ((const float4*)mean)[i];
    float4 g = ((const float4*)lgstd)[i];
    float4 e = ((const float4*)eps)[i];
    float4 w = make_float4(m.x + e.x * expf(g.x), m.y + e.y * expf(g.y),
                           m.z + e.z * expf(g.z), m.w + e.w * expf(g.w));
    __nv_bfloat162 h0, h1, l0, l1;
    bsplit(w.x, h0.x, l0.x); bsplit(w.y, h0.y, l0.y);
    bsplit(w.z, h1.x, l1.x); bsplit(w.w, h1.y, l1.y);
    ((__nv_bfloat162*)s_ow_hi)[2*i]   = h0;
    ((__nv_bfloat162*)s_ow_hi)[2*i+1] = h1;
    ((__nv_bfloat162*)s_ow_lo)[2*i]   = l0;
    ((__nv_bfloat162*)s_ow_lo)[2*i+1] = l1;
}

// =====================================================================
// bf16x3 HMMA GEMM NT: D[m,n] = sum_k A[m,k]*B[n,k]  (fp32 accumulate)
// CTA 128 x 64, BK=32 bf16; 8 warps (4 x 2); 2 CTAs/SM.
// 3-stage cp.async pipeline, wait_group 1 (next tile stays in flight).
// 3 terms: Ahi*Bhi + Ahi*Blo + Alo*Bhi.
// MODE 0: fp32 plain (Cf + z*sC + m*ldc + n)
// MODE 1: split + bias + scale -> q/k layout [bh][s][d]
// MODE 2: split + bias         -> v layout [bh][d][s]
// MODE 3: split                -> ctx layout [(q*BSZ+b)*EMB + h*HD + d]
// =====================================================================
template<int MODE>
__global__ __launch_bounds__(256, 2)
void gemm_mma(const __nv_bfloat16* __restrict__ Ahi, const __nv_bfloat16* __restrict__ Alo,
              const __nv_bfloat16* __restrict__ Bhi_, const __nv_bfloat16* __restrict__ Blo_,
              int lda, int ldb, int K,
              size_t sA, size_t sB, size_t sC,
              float* __restrict__ Cf, int ldc,
              __nv_bfloat16* __restrict__ Chi, __nv_bfloat16* __restrict__ Clo,
              const float* __restrict__ bias, float scale)
{
    constexpr int BM = 128, BN = 64, BK = 32;
    constexpr int WM = 2;                   // m16 frags per warp (4 warp-rows)
    constexpr int WN = 4;                   // n8 frags per warp  (2 warp-cols)
    constexpr int ABYTES = BM * 64;         // one matrix (hi or lo), 64B/row
    constexpr int BBYTES = BN * 64;
    constexpr int BUF = 2 * ABYTES + 2 * BBYTES;  // 24 KB per stage
    constexpr int NSTAGE = 3;

    extern __shared__ char smem[];
    const unsigned sb = smem_u32(smem);

    const int tid = threadIdx.x;
    const int l   = tid & 31;
    const int w   = tid >> 5;
    const int warp_m = (w & 3) * (WM * 16);   // 0,32,64,96
    const int warp_n = (w >> 2) * (WN * 8);   // 0,32

    const int z = blockIdx.z;
    Ahi  += (size_t)z * sA;  Alo  += (size_t)z * sA;
    Bhi_ += (size_t)z * sB;  Blo_ += (size_t)z * sB;
    const int blockM = blockIdx.y * BM;
    const int blockN = blockIdx.x * BN;

    float acc[WM][WN][4];
    #pragma unroll
    for (int i = 0; i < WM; i++)
        #pragma unroll
        for (int j = 0; j < WN; j++)
            #pragma unroll
            for (int r = 0; r < 4; r++) acc[i][j][r] = 0.f;

    const int NK = K / BK;
    const int aq = l >> 3, ar = l & 7;   // ldmatrix lane decomposition

    auto load_tile = [&](int kt, int buf) {
        const unsigned tb = sb + buf * BUF;
        #pragma unroll
        for (int t = 0; t < 2; t++) {                  // A: 512 chunks
            int i = tid + t * 256;
            int row = i >> 2, c = i & 3;
            size_t g = (size_t)(blockM + row) * lda + (size_t)kt * BK + c * 8;
            unsigned d = tb + swz(row, c);
            cpasync16(d,          Ahi + g);
            cpasync16(d + ABYTES, Alo + g);
        }
        {                                              // B: 256 chunks
            int row = tid >> 2, c = tid & 3;
            size_t g = (size_t)(blockN + row) * ldb + (size_t)kt * BK + c * 8;
            unsigned d = tb + 2 * ABYTES + swz(row, c);
            cpasync16(d,          Bhi_ + g);
            cpasync16(d + BBYTES, Blo_ + g);
        }
        CP_COMMIT();
    };

    load_tile(0, 0);
    if (NK > 1) load_tile(1, 1);

    int buf = 0, nbuf = (NK > 2) ? 2 : ((NK > 1) ? 0 : 1);
    for (int kt = 0; kt < NK; kt++) {
        if (kt + 1 < NK) { CP_WAIT1(); } else { CP_WAIT0(); }
        __syncthreads();
        if (kt + 2 < NK) {
            load_tile(kt + 2, nbuf);
        }
        const unsigned tb = sb + buf * BUF;

        #pragma unroll
        for (int ks = 0; ks < 2; ks++) {               // two k16 steps
            unsigned ah[WM][4], al_[WM][4];
            #pragma unroll
            for (int mi = 0; mi < WM; mi++) {
                int row = warp_m + mi * 16 + ar + 8 * (aq & 1);
                int c   = ks * 2 + (aq >> 1);
                unsigned ad = tb + swz(row, c);
                ldsm4(ah[mi],  ad);
                ldsm4(al_[mi], ad + ABYTES);
            }
            unsigned bh2[WN/2][4], bl2[WN/2][4];
            #pragma unroll
            for (int np = 0; np < WN / 2; np++) {
                int row = warp_n + np * 16 + ar + 8 * (aq >> 1);
                int c   = ks * 2 + (aq & 1);
                unsigned bd = tb + 2 * ABYTES + swz(row, c);
                ldsm4(bh2[np], bd);
                ldsm4(bl2[np], bd + BBYTES);
            }
            #pragma unroll
            for (int mi = 0; mi < WM; mi++)
                #pragma unroll
                for (int nj = 0; nj < WN; nj++) {
                    const unsigned* bh = &bh2[nj >> 1][(nj & 1) * 2];
                    const unsigned* bl = &bl2[nj >> 1][(nj & 1) * 2];
                    mma_bf16(acc[mi][nj], ah[mi],  bh[0], bh[1]);
                    mma_bf16(acc[mi][nj], ah[mi],  bl[0], bl[1]);
                    mma_bf16(acc[mi][nj], al_[mi], bh[0], bh[1]);
                }
        }
        buf = (buf + 1 == NSTAGE) ? 0 : buf + 1;
        nbuf = (nbuf + 1 == NSTAGE) ? 0 : nbuf + 1;
    }

    // ---------------- epilogue ----------------
    #pragma unroll
    for (int mi = 0; mi < WM; mi++) {
        #pragma unroll
        for (int nj = 0; nj < WN; nj++) {
            float* a = acc[mi][nj];
            const int m0 = blockM + warp_m + mi * 16 + (l >> 2);
            const int n0 = blockN + warp_n + nj * 8 + (l & 3) * 2;
            if (MODE == 0) {
                float* base = Cf + (size_t)z * sC;
                *(float2*)(base + (size_t)m0 * ldc + n0)       = make_float2(a[0], a[1]);
                *(float2*)(base + (size_t)(m0 + 8) * ldc + n0) = make_float2(a[2], a[3]);
            } else if (MODE == 1) {
                const float b0 = bias[n0], b1 = bias[n0 + 1];
                const int h = n0 >> 6, d = n0 & 63;
                #pragma unroll
                for (int r = 0; r < 2; r++) {
                    const int m = m0 + 8 * r;
                    const int b = m & 1, s = m >> 1;
                    float v0 = (a[2*r]   + b0) * scale;
                    float v1 = (a[2*r+1] + b1) * scale;
                    size_t o = ((size_t)(b * NH + h) * SEQ + s) * HD + d;
                    __nv_bfloat162 hh, ll;
                    bsplit(v0, hh.x, ll.x); bsplit(v1, hh.y, ll.y);
                    *(__nv_bfloat162*)(Chi + o) = hh;
                    *(__nv_bfloat162*)(Clo + o) = ll;
                }
            } else if (MODE == 2) {
                const float b0 = bias[n0], b1 = bias[n0 + 1];
                const int h = n0 >> 6, d = n0 & 63;
                #pragma unroll
                for (int r = 0; r < 2; r++) {
                    const int m = m0 + 8 * r;
                    const int b = m & 1, s = m >> 1;
                    float v0 = a[2*r]   + b0;
                    float v1 = a[2*r+1] + b1;
                    size_t o0 = ((size_t)(b * NH + h) * HD + d)     * SEQ + s;
                    size_t o1 = ((size_t)(b * NH + h) * HD + d + 1) * SEQ + s;
                    __nv_bfloat16 hh, ll;
                    bsplit(v0, hh, ll); Chi[o0] = hh; Clo[o0] = ll;
                    bsplit(v1, hh, ll); Chi[o1] = hh; Clo[o1] = ll;
                }
            } else {  // MODE 3: ctx
                const int b = z >> 4, h = z & 15;
                #pragma unroll
                for (int r = 0; r < 2; r++) {
                    const int m = m0 + 8 * r;
                    size_t o = ((size_t)m * BSZ + b) * EMB + h * HD + n0;
                    __nv_bfloat162 hh, ll;
                    bsplit(a[2*r],   hh.x, ll.x);
                    bsplit(a[2*r+1], hh.y, ll.y);
                    *(__nv_bfloat162*)(Chi + o) = hh;
                    *(__nv_bfloat162*)(Clo + o) = ll;
                }
            }
        }
    }
}

// ---------------- softmax + head-average + bf16 split ----------------
__device__ __forceinline__ float warpMax(float v) {
    #pragma unroll
    for (int o = 16; o; o >>= 1) v = fmaxf(v, __shfl_xor_sync(0xffffffffu, v, o));
    return v;
}
__device__ __forceinline__ float warpSum(float v) {
    #pragma unroll
    for (int o = 16; o; o >>= 1) v += __shfl_xor_sync(0xffffffffu, v, o);
    return v;
}

__global__ void softmax_avg_kernel(const float* __restrict__ attn,
                                   float* __restrict__ avg)
{
    __shared__ float red[8];
    const int bq = blockIdx.x;
    const int b = bq >> 11;          // SEQ = 2048
    const int q = bq & 2047;
    const int tid = threadIdx.x, lane = tid & 31, wid = tid >> 5;

    float4 a0 = make_float4(0.f, 0.f, 0.f, 0.f);
    float4 a1 = make_float4(0.f, 0.f, 0.f, 0.f);

    for (int h = 0; h < NH; h++) {
        const size_t rowoff = ((size_t)(b * NH + h) * SEQ + q) * SEQ;
        const float4* p4 = (const float4*)(attn + rowoff);
        float4 v0 = p4[tid];
        float4 v1 = p4[tid + 256];

        float mx = fmaxf(fmaxf(fmaxf(v0.x, v0.y), fmaxf(v0.z, v0.w)),
                         fmaxf(fmaxf(v1.x, v1.y), fmaxf(v1.z, v1.w)));
        mx = warpMax(mx);
        if (lane == 0) red[wid] = mx;
        __syncthreads();
        if (wid == 0) {
            float t = (lane < 8) ? red[lane] : -FLT_MAX;
            t = warpMax(t);
            if (lane == 0) red[0] = t;
        }
        __syncthreads();
        const float rowMax = red[0];
        __syncthreads();

        v0.x = __expf(v0.x - rowMax); v0.y = __expf(v0.y - rowMax);
        v0.z = __expf(v0.z - rowMax); v0.w = __expf(v0.w - rowMax);
        v1.x = __expf(v1.x - rowMax); v1.y = __expf(v1.y - rowMax);
        v1.z = __expf(v1.z - rowMax); v1.w = __expf(v1.w - rowMax);
        float sv = v0.x + v0.y + v0.z + v0.w + v1.x + v1.y + v1.z + v1.w;
        sv = warpSum(sv);
        if (lane == 0) red[wid] = sv;
        __syncthreads();
        if (wid == 0) {
            float t = (lane < 8) ? red[lane] : 0.f;
            t = warpSum(t);
            if (lane == 0) red[0] = t;
        }
        __syncthreads();
        const float inv = 1.f / red[0];
        __syncthreads();

        v0.x *= inv; v0.y *= inv; v0.z *= inv; v0.w *= inv;
        v1.x *= inv; v1.y *= inv; v1.z *= inv; v1.w *= inv;

        __nv_bfloat162* ph2 = (__nv_bfloat162*)(s_p_hi + rowoff);
        __nv_bfloat162* pl2 = (__nv_bfloat162*)(s_p_lo + rowoff);
        __nv_bfloat162 h0, h1, l0, l1;
        bsplit(v0.x, h0.x, l0.x); bsplit(v0.y, h0.y, l0.y);
        bsplit(v0.z, h1.x, l1.x); bsplit(v0.w, h1.y, l1.y);
        ph2[2*tid] = h0; ph2[2*tid+1] = h1;
        pl2[2*tid] = l0; pl2[2*tid+1] = l1;
        bsplit(v1.x, h0.x, l0.x); bsplit(v1.y, h0.y, l0.y);
        bsplit(v1.z, h1.x, l1.x); bsplit(v1.w, h1.y, l1.y);
        ph2[2*(tid+256)] = h0; ph2[2*(tid+256)+1] = h1;
        pl2[2*(tid+256)] = l0; pl2[2*(tid+256)+1] = l1;

        a0.x += v0.x; a0.y += v0.y; a0.z += v0.z; a0.w += v0.w;
        a1.x += v1.x; a1.y += v1.y; a1.z += v1.z; a1.w += v1.w;
    }

    const float invH = 1.f / NH;
    a0.x *= invH; a0.y *= invH; a0.z *= invH; a0.w *= invH;
    a1.x *= invH; a1.y *= invH; a1.z *= invH; a1.w *= invH;
    float4* o4 = (float4*)(avg + ((size_t)b * SEQ + q) * SEQ);
    o4[tid]       = a0;
    o4[tid + 256] = a1;
}

// ---------------- launch ----------------
extern "C" void kernel_launch(void* const* d_in, const int* in_sizes, int n_in,
                              void* d_out, int out_size)
{
    const float* query   = (const float*)d_in[0];
    const float* key     = (const float*)d_in[1];
    const float* value   = (const float*)d_in[2];
    const float* q_w     = (const float*)d_in[3];
    const float* q_b     = (const float*)d_in[4];
    const float* k_w     = (const float*)d_in[5];
    const float* k_b     = (const float*)d_in[6];
    const float* v_w     = (const float*)d_in[7];
    const float* v_b     = (const float*)d_in[8];
    const float* ow_mean = (const float*)d_in[9];
    const float* ow_lg   = (const float*)d_in[10];
    const float* eps     = (const float*)d_in[11];

    float* out_main = (float*)d_out;
    float* out_avg  = out_main + (size_t)MROWS * EMB;

    __nv_bfloat16 *xqh,*xql,*xkh,*xkl,*xvh,*xvl,*wqh,*wql,*wkh,*wkl,*wvh,*wvl;
    __nv_bfloat16 *owh,*owl,*qh,*ql,*kh,*kl,*vh,*vl,*pph,*ppl,*ch,*cl;
    float* attn_p;
    cudaGetSymbolAddress((void**)&xqh, s_xq_hi); cudaGetSymbolAddress((void**)&xql, s_xq_lo);
    cudaGetSymbolAddress((void**)&xkh, s_xk_hi); cudaGetSymbolAddress((void**)&xkl, s_xk_lo);
    cudaGetSymbolAddress((void**)&xvh, s_xv_hi); cudaGetSymbolAddress((void**)&xvl, s_xv_lo);
    cudaGetSymbolAddress((void**)&wqh, s_wq_hi); cudaGetSymbolAddress((void**)&wql, s_wq_lo);
    cudaGetSymbolAddress((void**)&wkh, s_wk_hi); cudaGetSymbolAddress((void**)&wkl, s_wk_lo);
    cudaGetSymbolAddress((void**)&wvh, s_wv_hi); cudaGetSymbolAddress((void**)&wvl, s_wv_lo);
    cudaGetSymbolAddress((void**)&owh, s_ow_hi); cudaGetSymbolAddress((void**)&owl, s_ow_lo);
    cudaGetSymbolAddress((void**)&qh,  s_q_hi);  cudaGetSymbolAddress((void**)&ql,  s_q_lo);
    cudaGetSymbolAddress((void**)&kh,  s_k_hi);  cudaGetSymbolAddress((void**)&kl,  s_k_lo);
    cudaGetSymbolAddress((void**)&vh,  s_v_hi);  cudaGetSymbolAddress((void**)&vl,  s_v_lo);
    cudaGetSymbolAddress((void**)&pph, s_p_hi);  cudaGetSymbolAddress((void**)&ppl, s_p_lo);
    cudaGetSymbolAddress((void**)&ch,  s_c_hi);  cudaGetSymbolAddress((void**)&cl,  s_c_lo);
    cudaGetSymbolAddress((void**)&attn_p, g_attn);

    // dynamic smem: 3 stages x 24 KB = 72 KB per CTA (2 CTAs/SM)
    const int SMEM = 3 * (2 * 128 * 64 + 2 * 64 * 64);
    cudaFuncSetAttribute(gemm_mma<0>, cudaFuncAttributeMaxDynamicSharedMemorySize, SMEM);
    cudaFuncSetAttribute(gemm_mma<1>, cudaFuncAttributeMaxDynamicSharedMemorySize, SMEM);
    cudaFuncSetAttribute(gemm_mma<2>, cudaFuncAttributeMaxDynamicSharedMemorySize, SMEM);
    cudaFuncSetAttribute(gemm_mma<3>, cudaFuncAttributeMaxDynamicSharedMemorySize, SMEM);

    // 1. fused split (launch #1), sampled output weight (launch #2)
    const int nx4 = MROWS * EMB / 4, nw4 = EMB * EMB / 4;
    {
        Split6Args a;
        a.src[0]=query; a.src[1]=key; a.src[2]=value;
        a.src[3]=q_w;   a.src[4]=k_w; a.src[5]=v_w;
        a.hi[0]=xqh; a.hi[1]=xkh; a.hi[2]=xvh; a.hi[3]=wqh; a.hi[4]=wkh; a.hi[5]=wvh;
        a.lo[0]=xql; a.lo[1]=xkl; a.lo[2]=xvl; a.lo[3]=wql; a.lo[4]=wkl; a.lo[5]=wvl;
        a.n4[0]=a.n4[1]=a.n4[2]=nx4; a.n4[3]=a.n4[4]=a.n4[5]=nw4;
        split6_kernel<<<dim3((nx4 + 255)/256, 6), 256>>>(a);
        ow_split_kernel<<<(nw4 + 255)/256, 256>>>(ow_mean, ow_lg, eps, nw4);
    }

    // 2. Q/K/V projections (launches #3,#4,#5)
    const dim3 gProj(EMB/64, MROWS/128, 1);
    gemm_mma<1><<<gProj, 256, SMEM>>>(xqh, xql, wqh, wql, EMB, EMB, EMB,
                                      0, 0, 0, nullptr, 0, qh, ql, q_b, 0.125f);
    gemm_mma<1><<<gProj, 256, SMEM>>>(xkh, xkl, wkh, wkl, EMB, EMB, EMB,
                                      0, 0, 0, nullptr, 0, kh, kl, k_b, 1.0f);
    gemm_mma<2><<<gProj, 256, SMEM>>>(xvh, xvl, wvh, wvl, EMB, EMB, EMB,
                                      0, 0, 0, nullptr, 0, vh, vl, v_b, 1.0f);

    // 3. scores = Q K^T (launch #6 — ncu -s 5 -c 1 captures this one)
    const dim3 gScore(SEQ/64, SEQ/128, BH);
    gemm_mma<0><<<gScore, 256, SMEM>>>(qh, ql, kh, kl, HD, HD, HD,
                                       (size_t)SEQ*HD, (size_t)SEQ*HD,
                                       (size_t)SEQ*SEQ, attn_p, SEQ,
                                       nullptr, nullptr, nullptr, 1.0f);

    // 4. softmax + avg + bf16 split of probs
    softmax_avg_kernel<<<BSZ*SEQ, 256>>>(attn_p, out_avg);

    // 5. ctx = P @ V  (batched; V stored [bh][d][s] -> NT form)
    const dim3 gCtx(1, SEQ/128, BH);
    gemm_mma<3><<<gCtx, 256, SMEM>>>(pph, ppl, vh, vl, SEQ, SEQ, SEQ,
                                     (size_t)SEQ*SEQ, (size_t)HD*SEQ, 0,
                                     nullptr, 0, ch, cl, nullptr, 1.0f);

    // 6. out = ctx @ o_w^T  (fp32 out)
    const dim3 gOut(EMB/64, MROWS/128, 1);
    gemm_mma<0><<<gOut, 256, SMEM>>>(ch, cl, owh, owl, EMB, EMB, EMB,
                                     0, 0, 0, out_main, EMB,
                                     nullptr, nullptr, nullptr, 1.0f);
}

// round 8
// speedup vs baseline: 1.0844x; 1.0844x over previous
#include <cuda_runtime.h>
#include <cuda_bf16.h>
#include <math.h>
#include <float.h>

// ---------------- problem constants ----------------
#define SEQ  2048
#define BSZ  2
#define EMB  1024
#define NH   16
#define HD   64
#define BH   (BSZ*NH)          // 32
#define MROWS (SEQ*BSZ)        // 4096

// ---------------- scratch (static device arrays) ----------------
__device__ __align__(1024) __nv_bfloat16 s_xq_hi[(size_t)MROWS*EMB];
__device__ __align__(1024) __nv_bfloat16 s_xq_lo[(size_t)MROWS*EMB];
__device__ __align__(1024) __nv_bfloat16 s_xk_hi[(size_t)MROWS*EMB];
__device__ __align__(1024) __nv_bfloat16 s_xk_lo[(size_t)MROWS*EMB];
__device__ __align__(1024) __nv_bfloat16 s_xv_hi[(size_t)MROWS*EMB];
__device__ __align__(1024) __nv_bfloat16 s_xv_lo[(size_t)MROWS*EMB];
__device__ __align__(1024) __nv_bfloat16 s_wq_hi[(size_t)EMB*EMB];
__device__ __align__(1024) __nv_bfloat16 s_wq_lo[(size_t)EMB*EMB];
__device__ __align__(1024) __nv_bfloat16 s_wk_hi[(size_t)EMB*EMB];
__device__ __align__(1024) __nv_bfloat16 s_wk_lo[(size_t)EMB*EMB];
__device__ __align__(1024) __nv_bfloat16 s_wv_hi[(size_t)EMB*EMB];
__device__ __align__(1024) __nv_bfloat16 s_wv_lo[(size_t)EMB*EMB];
__device__ __align__(1024) __nv_bfloat16 s_ow_hi[(size_t)EMB*EMB];
__device__ __align__(1024) __nv_bfloat16 s_ow_lo[(size_t)EMB*EMB];
__device__ __align__(1024) __nv_bfloat16 s_q_hi[(size_t)BH*SEQ*HD];
__device__ __align__(1024) __nv_bfloat16 s_q_lo[(size_t)BH*SEQ*HD];
__device__ __align__(1024) __nv_bfloat16 s_k_hi[(size_t)BH*SEQ*HD];
__device__ __align__(1024) __nv_bfloat16 s_k_lo[(size_t)BH*SEQ*HD];
__device__ __align__(1024) __nv_bfloat16 s_v_hi[(size_t)BH*HD*SEQ];  // [bh][d][s]
__device__ __align__(1024) __nv_bfloat16 s_v_lo[(size_t)BH*HD*SEQ];
__device__ __align__(1024) float         g_attn[(size_t)BH*SEQ*SEQ]; // 512 MB
__device__ __align__(1024) __nv_bfloat16 s_p_hi[(size_t)BH*SEQ*SEQ]; // 256 MB
__device__ __align__(1024) __nv_bfloat16 s_p_lo[(size_t)BH*SEQ*SEQ]; // 256 MB
__device__ __align__(1024) __nv_bfloat16 s_c_hi[(size_t)MROWS*EMB];
__device__ __align__(1024) __nv_bfloat16 s_c_lo[(size_t)MROWS*EMB];

// ---------------- PTX helpers ----------------
__device__ __forceinline__ unsigned smem_u32(const void* p) {
    unsigned a;
    asm("{ .reg .u64 t; cvta.to.shared.u64 t, %1; cvt.u32.u64 %0, t; }"
        : "=r"(a) : "l"(p));
    return a;
}
__device__ __forceinline__ void cpasync16(unsigned dst, const void* src) {
    asm volatile("cp.async.cg.shared.global [%0], [%1], 16;" :: "r"(dst), "l"(src));
}
#define CP_COMMIT() asm volatile("cp.async.commit_group;" ::: "memory")
#define CP_WAIT0()  asm volatile("cp.async.wait_group 0;" ::: "memory")

__device__ __forceinline__ void ldsm4(unsigned r[4], unsigned addr) {
    asm volatile("ldmatrix.sync.aligned.m8n8.x4.shared.b16 {%0,%1,%2,%3}, [%4];"
        : "=r"(r[0]), "=r"(r[1]), "=r"(r[2]), "=r"(r[3]) : "r"(addr));
}
__device__ __forceinline__ void mma_bf16(float* d, const unsigned a[4],
                                         unsigned b0, unsigned b1) {
    asm volatile("mma.sync.aligned.m16n8k16.row.col.f32.bf16.bf16.f32 "
        "{%0,%1,%2,%3}, {%4,%5,%6,%7}, {%8,%9}, {%0,%1,%2,%3};"
        : "+f"(d[0]), "+f"(d[1]), "+f"(d[2]), "+f"(d[3])
        : "r"(a[0]), "r"(a[1]), "r"(a[2]), "r"(a[3]), "r"(b0), "r"(b1));
}
__device__ __forceinline__ void bsplit(float v, __nv_bfloat16& h, __nv_bfloat16& l) {
    h = __float2bfloat16(v);
    l = __float2bfloat16(v - __bfloat162float(h));
}
// SW128 swizzle within a tile of 128B rows (8 x 16B chunks per row)
__device__ __forceinline__ unsigned swz(int row, int chunk) {
    return (unsigned)(row * 128 + ((chunk ^ (row & 7)) << 4));
}

// ---------------- fused conversion kernels ----------------
struct Split6Args {
    const float*   src[6];
    __nv_bfloat16* hi[6];
    __nv_bfloat16* lo[6];
    int            n4[6];
};

__global__ void split6_kernel(Split6Args a)
{
    const int z = blockIdx.y;
    int i = blockIdx.x * blockDim.x + threadIdx.x;
    if (i >= a.n4[z]) return;
    float4 v = ((const float4*)a.src[z])[i];
    __nv_bfloat162 h0, h1, l0, l1;
    bsplit(v.x, h0.x, l0.x); bsplit(v.y, h0.y, l0.y);
    bsplit(v.z, h1.x, l1.x); bsplit(v.w, h1.y, l1.y);
    ((__nv_bfloat162*)a.hi[z])[2*i]   = h0;
    ((__nv_bfloat162*)a.hi[z])[2*i+1] = h1;
    ((__nv_bfloat162*)a.lo[z])[2*i]   = l0;
    ((__nv_bfloat162*)a.lo[z])[2*i+1] = l1;
}

__global__ void ow_split_kernel(const float* __restrict__ mean,
                                const float* __restrict__ lgstd,
                                const float* __restrict__ eps, int n4)
{
    int i = blockIdx.x * blockDim.x + threadIdx.x;
    if (i >= n4) return;
    float4 m = ((const float4*)mean)[i];
    float4 g = ((const float4*)lgstd)[i];
    float4 e = ((const float4*)eps)[i];
    float4 w = make_float4(m.x + e.x * expf(g.x), m.y + e.y * expf(g.y),
                           m.z + e.z * expf(g.z), m.w + e.w * expf(g.w));
    __nv_bfloat162 h0, h1, l0, l1;
    bsplit(w.x, h0.x, l0.x); bsplit(w.y, h0.y, l0.y);
    bsplit(w.z, h1.x, l1.x); bsplit(w.w, h1.y, l1.y);
    ((__nv_bfloat162*)s_ow_hi)[2*i]   = h0;
    ((__nv_bfloat162*)s_ow_hi)[2*i+1] = h1;
    ((__nv_bfloat162*)s_ow_lo)[2*i]   = l0;
    ((__nv_bfloat162*)s_ow_lo)[2*i+1] = l1;
}

// =====================================================================
// bf16x3 HMMA GEMM NT: D[m,n] = sum_k A[m,k]*B[n,k]  (fp32 accumulate)
// CTA 128 x 64, BK=64 bf16 (128B rows, SW128); 8 warps (4 x 2); 2 CTAs/SM.
// 2-stage cp.async double buffer; hi-fragment register pipelining.
// 3 terms: Ahi*Bhi + Ahi*Blo + Alo*Bhi.
// MODE 0: fp32 plain (Cf + z*sC + m*ldc + n)
// MODE 1: split + bias + scale -> q/k layout [bh][s][d]
// MODE 2: split + bias         -> v layout [bh][d][s]
// MODE 3: split                -> ctx layout [(q*BSZ+b)*EMB + h*HD + d]
// =====================================================================
template<int MODE>
__global__ __launch_bounds__(256, 2)
void gemm_mma(const __nv_bfloat16* __restrict__ Ahi, const __nv_bfloat16* __restrict__ Alo,
              const __nv_bfloat16* __restrict__ Bhi_, const __nv_bfloat16* __restrict__ Blo_,
              int lda, int ldb, int K,
              size_t sA, size_t sB, size_t sC,
              float* __restrict__ Cf, int ldc,
              __nv_bfloat16* __restrict__ Chi, __nv_bfloat16* __restrict__ Clo,
              const float* __restrict__ bias, float scale)
{
    constexpr int BM = 128, BN = 64, BK = 64;
    constexpr int WM = 2;                   // m16 frags per warp (4 warp-rows)
    constexpr int WN = 4;                   // n8 frags per warp  (2 warp-cols)
    constexpr int ABYTES = BM * 128;        // one matrix (hi or lo), 128B/row
    constexpr int BBYTES = BN * 128;
    constexpr int BUF = 2 * ABYTES + 2 * BBYTES;  // 48 KB per stage

    extern __shared__ char smem[];
    const unsigned sb = smem_u32(smem);

    const int tid = threadIdx.x;
    const int l   = tid & 31;
    const int w   = tid >> 5;
    const int warp_m = (w & 3) * (WM * 16);   // 0,32,64,96
    const int warp_n = (w >> 2) * (WN * 8);   // 0,32

    const int z = blockIdx.z;
    Ahi  += (size_t)z * sA;  Alo  += (size_t)z * sA;
    Bhi_ += (size_t)z * sB;  Blo_ += (size_t)z * sB;
    const int blockM = blockIdx.y * BM;
    const int blockN = blockIdx.x * BN;

    float acc[WM][WN][4];
    #pragma unroll
    for (int i = 0; i < WM; i++)
        #pragma unroll
        for (int j = 0; j < WN; j++)
            #pragma unroll
            for (int r = 0; r < 4; r++) acc[i][j][r] = 0.f;

    const int NK = K / BK;
    const int aq = l >> 3, ar = l & 7;   // ldmatrix lane decomposition

    // per-lane fragment smem row/chunk bases (chunk varies with ks)
    const int arow_f = warp_m + ar + 8 * (aq & 1);   // + mi*16
    const int acol_f = (aq >> 1);                    // + ks*2
    const int brow_f = warp_n + ar + 8 * (aq >> 1);  // + np*16
    const int bcol_f = (aq & 1);                     // + ks*2

    auto load_tile = [&](int kt, int buf) {
        const unsigned tb = sb + buf * BUF;
        #pragma unroll
        for (int t = 0; t < 4; t++) {                  // A: 1024 chunks/matrix
            int i = tid + t * 256;
            int row = i >> 3, c = i & 7;
            size_t g = (size_t)(blockM + row) * lda + (size_t)kt * BK + c * 8;
            unsigned d = tb + swz(row, c);
            cpasync16(d,          Ahi + g);
            cpasync16(d + ABYTES, Alo + g);
        }
        #pragma unroll
        for (int t = 0; t < 2; t++) {                  // B: 512 chunks/matrix
            int i = tid + t * 256;
            int row = i >> 3, c = i & 7;
            size_t g = (size_t)(blockN + row) * ldb + (size_t)kt * BK + c * 8;
            unsigned d = tb + 2 * ABYTES + swz(row, c);
            cpasync16(d,          Bhi_ + g);
            cpasync16(d + BBYTES, Blo_ + g);
        }
        CP_COMMIT();
    };

    load_tile(0, 0);

    unsigned ah[2][WM][4], bh[2][WN/2][4];   // hi frags, double buffered
    unsigned al_[WM][4], bl[WN/2][4];        // lo frags, just-in-time

    for (int kt = 0; kt < NK; kt++) {
        CP_WAIT0();
        __syncthreads();
        const unsigned tb = sb + (kt & 1) * BUF;

        // preload ks=0 hi frags
        #pragma unroll
        for (int mi = 0; mi < WM; mi++)
            ldsm4(ah[0][mi], tb + swz(arow_f + mi * 16, acol_f));
        #pragma unroll
        for (int np = 0; np < WN / 2; np++)
            ldsm4(bh[0][np], tb + 2 * ABYTES + swz(brow_f + np * 16, bcol_f));

        if (kt + 1 < NK) load_tile(kt + 1, (kt + 1) & 1);

        #pragma unroll
        for (int ks = 0; ks < 4; ks++) {               // four k16 steps
            const int cur = ks & 1, nxt = cur ^ 1;
            // lo frags for this step (latency hidden by hi*hi MMAs below)
            #pragma unroll
            for (int mi = 0; mi < WM; mi++)
                ldsm4(al_[mi], tb + ABYTES + swz(arow_f + mi * 16, ks * 2 + acol_f));
            #pragma unroll
            for (int np = 0; np < WN / 2; np++)
                ldsm4(bl[np], tb + 2 * ABYTES + BBYTES + swz(brow_f + np * 16, ks * 2 + bcol_f));

            // hi * hi
            #pragma unroll
            for (int mi = 0; mi < WM; mi++)
                #pragma unroll
                for (int nj = 0; nj < WN; nj++) {
                    const unsigned* bhf = &bh[cur][nj >> 1][(nj & 1) * 2];
                    mma_bf16(acc[mi][nj], ah[cur][mi], bhf[0], bhf[1]);
                }

            // prefetch next hi frags
            if (ks < 3) {
                #pragma unroll
                for (int mi = 0; mi < WM; mi++)
                    ldsm4(ah[nxt][mi], tb + swz(arow_f + mi * 16, (ks + 1) * 2 + acol_f));
                #pragma unroll
                for (int np = 0; np < WN / 2; np++)
                    ldsm4(bh[nxt][np], tb + 2 * ABYTES + swz(brow_f + np * 16, (ks + 1) * 2 + bcol_f));
            }

            // cross terms: hi*lo + lo*hi
            #pragma unroll
            for (int mi = 0; mi < WM; mi++)
                #pragma unroll
                for (int nj = 0; nj < WN; nj++) {
                    const unsigned* bhf = &bh[cur][nj >> 1][(nj & 1) * 2];
                    const unsigned* blf = &bl[nj >> 1][(nj & 1) * 2];
                    mma_bf16(acc[mi][nj], ah[cur][mi], blf[0], blf[1]);
                    mma_bf16(acc[mi][nj], al_[mi],     bhf[0], bhf[1]);
                }
        }
    }

    // ---------------- epilogue ----------------
    #pragma unroll
    for (int mi = 0; mi < WM; mi++) {
        #pragma unroll
        for (int nj = 0; nj < WN; nj++) {
            float* a = acc[mi][nj];
            const int m0 = blockM + warp_m + mi * 16 + (l >> 2);
            const int n0 = blockN + warp_n + nj * 8 + (l & 3) * 2;
            if (MODE == 0) {
                float* base = Cf + (size_t)z * sC;
                *(float2*)(base + (size_t)m0 * ldc + n0)       = make_float2(a[0], a[1]);
                *(float2*)(base + (size_t)(m0 + 8) * ldc + n0) = make_float2(a[2], a[3]);
            } else if (MODE == 1) {
                const float b0 = bias[n0], b1 = bias[n0 + 1];
                const int h = n0 >> 6, d = n0 & 63;
                #pragma unroll
                for (int r = 0; r < 2; r++) {
                    const int m = m0 + 8 * r;
                    const int b = m & 1, s = m >> 1;
                    float v0 = (a[2*r]   + b0) * scale;
                    float v1 = (a[2*r+1] + b1) * scale;
                    size_t o = ((size_t)(b * NH + h) * SEQ + s) * HD + d;
                    __nv_bfloat162 hh, ll;
                    bsplit(v0, hh.x, ll.x); bsplit(v1, hh.y, ll.y);
                    *(__nv_bfloat162*)(Chi + o) = hh;
                    *(__nv_bfloat162*)(Clo + o) = ll;
                }
            } else if (MODE == 2) {
                const float b0 = bias[n0], b1 = bias[n0 + 1];
                const int h = n0 >> 6, d = n0 & 63;
                #pragma unroll
                for (int r = 0; r < 2; r++) {
                    const int m = m0 + 8 * r;
                    const int b = m & 1, s = m >> 1;
                    float v0 = a[2*r]   + b0;
                    float v1 = a[2*r+1] + b1;
                    size_t o0 = ((size_t)(b * NH + h) * HD + d)     * SEQ + s;
                    size_t o1 = ((size_t)(b * NH + h) * HD + d + 1) * SEQ + s;
                    __nv_bfloat16 hh, ll;
                    bsplit(v0, hh, ll); Chi[o0] = hh; Clo[o0] = ll;
                    bsplit(v1, hh, ll); Chi[o1] = hh; Clo[o1] = ll;
                }
            } else {  // MODE 3: ctx
                const int b = z >> 4, h = z & 15;
                #pragma unroll
                for (int r = 0; r < 2; r++) {
                    const int m = m0 + 8 * r;
                    size_t o = ((size_t)m * BSZ + b) * EMB + h * HD + n0;
                    __nv_bfloat162 hh, ll;
                    bsplit(a[2*r],   hh.x, ll.x);
                    bsplit(a[2*r+1], hh.y, ll.y);
                    *(__nv_bfloat162*)(Chi + o) = hh;
                    *(__nv_bfloat162*)(Clo + o) = ll;
                }
            }
        }
    }
}

// ---------------- softmax + head-average + bf16 split ----------------
__device__ __forceinline__ float warpMax(float v) {
    #pragma unroll
    for (int o = 16; o; o >>= 1) v = fmaxf(v, __shfl_xor_sync(0xffffffffu, v, o));
    return v;
}
__device__ __forceinline__ float warpSum(float v) {
    #pragma unroll
    for (int o = 16; o; o >>= 1) v += __shfl_xor_sync(0xffffffffu, v, o);
    return v;
}

__global__ void softmax_avg_kernel(const float* __restrict__ attn,
                                   float* __restrict__ avg)
{
    __shared__ float red[8];
    const int bq = blockIdx.x;
    const int b = bq >> 11;          // SEQ = 2048
    const int q = bq & 2047;
    const int tid = threadIdx.x, lane = tid & 31, wid = tid >> 5;

    float4 a0 = make_float4(0.f, 0.f, 0.f, 0.f);
    float4 a1 = make_float4(0.f, 0.f, 0.f, 0.f);

    for (int h = 0; h < NH; h++) {
        const size_t rowoff = ((size_t)(b * NH + h) * SEQ + q) * SEQ;
        const float4* p4 = (const float4*)(attn + rowoff);
        float4 v0 = p4[tid];
        float4 v1 = p4[tid + 256];

        float mx = fmaxf(fmaxf(fmaxf(v0.x, v0.y), fmaxf(v0.z, v0.w)),
                         fmaxf(fmaxf(v1.x, v1.y), fmaxf(v1.z, v1.w)));
        mx = warpMax(mx);
        if (lane == 0) red[wid] = mx;
        __syncthreads();
        if (wid == 0) {
            float t = (lane < 8) ? red[lane] : -FLT_MAX;
            t = warpMax(t);
            if (lane == 0) red[0] = t;
        }
        __syncthreads();
        const float rowMax = red[0];
        __syncthreads();

        v0.x = __expf(v0.x - rowMax); v0.y = __expf(v0.y - rowMax);
        v0.z = __expf(v0.z - rowMax); v0.w = __expf(v0.w - rowMax);
        v1.x = __expf(v1.x - rowMax); v1.y = __expf(v1.y - rowMax);
        v1.z = __expf(v1.z - rowMax); v1.w = __expf(v1.w - rowMax);
        float sv = v0.x + v0.y + v0.z + v0.w + v1.x + v1.y + v1.z + v1.w;
        sv = warpSum(sv);
        if (lane == 0) red[wid] = sv;
        __syncthreads();
        if (wid == 0) {
            float t = (lane < 8) ? red[lane] : 0.f;
            t = warpSum(t);
            if (lane == 0) red[0] = t;
        }
        __syncthreads();
        const float inv = 1.f / red[0];
        __syncthreads();

        v0.x *= inv; v0.y *= inv; v0.z *= inv; v0.w *= inv;
        v1.x *= inv; v1.y *= inv; v1.z *= inv; v1.w *= inv;

        __nv_bfloat162* ph2 = (__nv_bfloat162*)(s_p_hi + rowoff);
        __nv_bfloat162* pl2 = (__nv_bfloat162*)(s_p_lo + rowoff);
        __nv_bfloat162 h0, h1, l0, l1;
        bsplit(v0.x, h0.x, l0.x); bsplit(v0.y, h0.y, l0.y);
        bsplit(v0.z, h1.x, l1.x); bsplit(v0.w, h1.y, l1.y);
        ph2[2*tid] = h0; ph2[2*tid+1] = h1;
        pl2[2*tid] = l0; pl2[2*tid+1] = l1;
        bsplit(v1.x, h0.x, l0.x); bsplit(v1.y, h0.y, l0.y);
        bsplit(v1.z, h1.x, l1.x); bsplit(v1.w, h1.y, l1.y);
        ph2[2*(tid+256)] = h0; ph2[2*(tid+256)+1] = h1;
        pl2[2*(tid+256)] = l0; pl2[2*(tid+256)+1] = l1;

        a0.x += v0.x; a0.y += v0.y; a0.z += v0.z; a0.w += v0.w;
        a1.x += v1.x; a1.y += v1.y; a1.z += v1.z; a1.w += v1.w;
    }

    const float invH = 1.f / NH;
    a0.x *= invH; a0.y *= invH; a0.z *= invH; a0.w *= invH;
    a1.x *= invH; a1.y *= invH; a1.z *= invH; a1.w *= invH;
    float4* o4 = (float4*)(avg + ((size_t)b * SEQ + q) * SEQ);
    o4[tid]       = a0;
    o4[tid + 256] = a1;
}

// ---------------- launch ----------------
extern "C" void kernel_launch(void* const* d_in, const int* in_sizes, int n_in,
                              void* d_out, int out_size)
{
    const float* query   = (const float*)d_in[0];
    const float* key     = (const float*)d_in[1];
    const float* value   = (const float*)d_in[2];
    const float* q_w     = (const float*)d_in[3];
    const float* q_b     = (const float*)d_in[4];
    const float* k_w     = (const float*)d_in[5];
    const float* k_b     = (const float*)d_in[6];
    const float* v_w     = (const float*)d_in[7];
    const float* v_b     = (const float*)d_in[8];
    const float* ow_mean = (const float*)d_in[9];
    const float* ow_lg   = (const float*)d_in[10];
    const float* eps     = (const float*)d_in[11];

    float* out_main = (float*)d_out;
    float* out_avg  = out_main + (size_t)MROWS * EMB;

    __nv_bfloat16 *xqh,*xql,*xkh,*xkl,*xvh,*xvl,*wqh,*wql,*wkh,*wkl,*wvh,*wvl;
    __nv_bfloat16 *owh,*owl,*qh,*ql,*kh,*kl,*vh,*vl,*pph,*ppl,*ch,*cl;
    float* attn_p;
    cudaGetSymbolAddress((void**)&xqh, s_xq_hi); cudaGetSymbolAddress((void**)&xql, s_xq_lo);
    cudaGetSymbolAddress((void**)&xkh, s_xk_hi); cudaGetSymbolAddress((void**)&xkl, s_xk_lo);
    cudaGetSymbolAddress((void**)&xvh, s_xv_hi); cudaGetSymbolAddress((void**)&xvl, s_xv_lo);
    cudaGetSymbolAddress((void**)&wqh, s_wq_hi); cudaGetSymbolAddress((void**)&wql, s_wq_lo);
    cudaGetSymbolAddress((void**)&wkh, s_wk_hi); cudaGetSymbolAddress((void**)&wkl, s_wk_lo);
    cudaGetSymbolAddress((void**)&wvh, s_wv_hi); cudaGetSymbolAddress((void**)&wvl, s_wv_lo);
    cudaGetSymbolAddress((void**)&owh, s_ow_hi); cudaGetSymbolAddress((void**)&owl, s_ow_lo);
    cudaGetSymbolAddress((void**)&qh,  s_q_hi);  cudaGetSymbolAddress((void**)&ql,  s_q_lo);
    cudaGetSymbolAddress((void**)&kh,  s_k_hi);  cudaGetSymbolAddress((void**)&kl,  s_k_lo);
    cudaGetSymbolAddress((void**)&vh,  s_v_hi);  cudaGetSymbolAddress((void**)&vl,  s_v_lo);
    cudaGetSymbolAddress((void**)&pph, s_p_hi);  cudaGetSymbolAddress((void**)&ppl, s_p_lo);
    cudaGetSymbolAddress((void**)&ch,  s_c_hi);  cudaGetSymbolAddress((void**)&cl,  s_c_lo);
    cudaGetSymbolAddress((void**)&attn_p, g_attn);

    // dynamic smem: 2 stages x 48 KB = 96 KB per CTA (2 CTAs/SM)
    const int SMEM = 2 * (2 * 128 * 128 + 2 * 64 * 128);
    cudaFuncSetAttribute(gemm_mma<0>, cudaFuncAttributeMaxDynamicSharedMemorySize, SMEM);
    cudaFuncSetAttribute(gemm_mma<1>, cudaFuncAttributeMaxDynamicSharedMemorySize, SMEM);
    cudaFuncSetAttribute(gemm_mma<2>, cudaFuncAttributeMaxDynamicSharedMemorySize, SMEM);
    cudaFuncSetAttribute(gemm_mma<3>, cudaFuncAttributeMaxDynamicSharedMemorySize, SMEM);

    // 1. fused split (launch #1), sampled output weight (launch #2)
    const int nx4 = MROWS * EMB / 4, nw4 = EMB * EMB / 4;
    {
        Split6Args a;
        a.src[0]=query; a.src[1]=key; a.src[2]=value;
        a.src[3]=q_w;   a.src[4]=k_w; a.src[5]=v_w;
        a.hi[0]=xqh; a.hi[1]=xkh; a.hi[2]=xvh; a.hi[3]=wqh; a.hi[4]=wkh; a.hi[5]=wvh;
        a.lo[0]=xql; a.lo[1]=xkl; a.lo[2]=xvl; a.lo[3]=wql; a.lo[4]=wkl; a.lo[5]=wvl;
        a.n4[0]=a.n4[1]=a.n4[2]=nx4; a.n4[3]=a.n4[4]=a.n4[5]=nw4;
        split6_kernel<<<dim3((nx4 + 255)/256, 6), 256>>>(a);
        ow_split_kernel<<<(nw4 + 255)/256, 256>>>(ow_mean, ow_lg, eps, nw4);
    }

    // 2. Q/K/V projections (launches #3,#4,#5)
    const dim3 gProj(EMB/64, MROWS/128, 1);
    gemm_mma<1><<<gProj, 256, SMEM>>>(xqh, xql, wqh, wql, EMB, EMB, EMB,
                                      0, 0, 0, nullptr, 0, qh, ql, q_b, 0.125f);
    gemm_mma<1><<<gProj, 256, SMEM>>>(xkh, xkl, wkh, wkl, EMB, EMB, EMB,
                                      0, 0, 0, nullptr, 0, kh, kl, k_b, 1.0f);
    gemm_mma<2><<<gProj, 256, SMEM>>>(xvh, xvl, wvh, wvl, EMB, EMB, EMB,
                                      0, 0, 0, nullptr, 0, vh, vl, v_b, 1.0f);

    // 3. scores = Q K^T (launch #6 — ncu -s 5 -c 1 captures this one)
    const dim3 gScore(SEQ/64, SEQ/128, BH);
    gemm_mma<0><<<gScore, 256, SMEM>>>(qh, ql, kh, kl, HD, HD, HD,
                                       (size_t)SEQ*HD, (size_t)SEQ*HD,
                                       (size_t)SEQ*SEQ, attn_p, SEQ,
                                       nullptr, nullptr, nullptr, 1.0f);

    // 4. softmax + avg + bf16 split of probs
    softmax_avg_kernel<<<BSZ*SEQ, 256>>>(attn_p, out_avg);

    // 5. ctx = P @ V  (batched; V stored [bh][d][s] -> NT form)
    const dim3 gCtx(1, SEQ/128, BH);
    gemm_mma<3><<<gCtx, 256, SMEM>>>(pph, ppl, vh, vl, SEQ, SEQ, SEQ,
                                     (size_t)SEQ*SEQ, (size_t)HD*SEQ, 0,
                                     nullptr, 0, ch, cl, nullptr, 1.0f);

    // 6. out = ctx @ o_w^T  (fp32 out)
    const dim3 gOut(EMB/64, MROWS/128, 1);
    gemm_mma<0><<<gOut, 256, SMEM>>>(ch, cl, owh, owl, EMB, EMB, EMB,
                                     0, 0, 0, out_main, EMB,
                                     nullptr, nullptr, nullptr, 1.0f);
}

// round 9
// speedup vs baseline: 1.1375x; 1.0490x over previous
#include <cuda_runtime.h>
#include <cuda_bf16.h>
#include <math.h>
#include <float.h>

// ---------------- problem constants ----------------
#define SEQ  2048
#define BSZ  2
#define EMB  1024
#define NH   16
#define HD   64
#define BH   (BSZ*NH)          // 32
#define MROWS (SEQ*BSZ)        // 4096

// ---------------- scratch (static device arrays) ----------------
__device__ __align__(1024) __nv_bfloat16 s_xq_hi[(size_t)MROWS*EMB];
__device__ __align__(1024) __nv_bfloat16 s_xq_lo[(size_t)MROWS*EMB];
__device__ __align__(1024) __nv_bfloat16 s_xk_hi[(size_t)MROWS*EMB];
__device__ __align__(1024) __nv_bfloat16 s_xk_lo[(size_t)MROWS*EMB];
__device__ __align__(1024) __nv_bfloat16 s_xv_hi[(size_t)MROWS*EMB];
__device__ __align__(1024) __nv_bfloat16 s_xv_lo[(size_t)MROWS*EMB];
__device__ __align__(1024) __nv_bfloat16 s_wq_hi[(size_t)EMB*EMB];
__device__ __align__(1024) __nv_bfloat16 s_wq_lo[(size_t)EMB*EMB];
__device__ __align__(1024) __nv_bfloat16 s_wk_hi[(size_t)EMB*EMB];
__device__ __align__(1024) __nv_bfloat16 s_wk_lo[(size_t)EMB*EMB];
__device__ __align__(1024) __nv_bfloat16 s_wv_hi[(size_t)EMB*EMB];
__device__ __align__(1024) __nv_bfloat16 s_wv_lo[(size_t)EMB*EMB];
__device__ __align__(1024) __nv_bfloat16 s_ow_hi[(size_t)EMB*EMB];
__device__ __align__(1024) __nv_bfloat16 s_ow_lo[(size_t)EMB*EMB];
__device__ __align__(1024) __nv_bfloat16 s_q_hi[(size_t)BH*SEQ*HD];
__device__ __align__(1024) __nv_bfloat16 s_q_lo[(size_t)BH*SEQ*HD];
__device__ __align__(1024) __nv_bfloat16 s_k_hi[(size_t)BH*SEQ*HD];
__device__ __align__(1024) __nv_bfloat16 s_k_lo[(size_t)BH*SEQ*HD];
__device__ __align__(1024) __nv_bfloat16 s_v_hi[(size_t)BH*HD*SEQ];  // [bh][d][s]
__device__ __align__(1024) __nv_bfloat16 s_v_lo[(size_t)BH*HD*SEQ];
__device__ __align__(1024) float         g_attn[(size_t)BH*SEQ*SEQ]; // 512 MB
__device__ __align__(1024) __nv_bfloat16 s_p_hi[(size_t)BH*SEQ*SEQ]; // 256 MB
__device__ __align__(1024) __nv_bfloat16 s_p_lo[(size_t)BH*SEQ*SEQ]; // 256 MB
__device__ __align__(1024) __nv_bfloat16 s_c_hi[(size_t)MROWS*EMB];
__device__ __align__(1024) __nv_bfloat16 s_c_lo[(size_t)MROWS*EMB];

// ---------------- PTX helpers ----------------
__device__ __forceinline__ unsigned smem_u32(const void* p) {
    unsigned a;
    asm("{ .reg .u64 t; cvta.to.shared.u64 t, %1; cvt.u32.u64 %0, t; }"
        : "=r"(a) : "l"(p));
    return a;
}
__device__ __forceinline__ void cpasync16(unsigned dst, const void* src) {
    asm volatile("cp.async.cg.shared.global [%0], [%1], 16;" :: "r"(dst), "l"(src));
}
#define CP_COMMIT() asm volatile("cp.async.commit_group;" ::: "memory")
#define CP_WAIT0()  asm volatile("cp.async.wait_group 0;" ::: "memory")

__device__ __forceinline__ void ldsm4(unsigned r[4], unsigned addr) {
    asm volatile("ldmatrix.sync.aligned.m8n8.x4.shared.b16 {%0,%1,%2,%3}, [%4];"
        : "=r"(r[0]), "=r"(r[1]), "=r"(r[2]), "=r"(r[3]) : "r"(addr));
}
__device__ __forceinline__ void mma_bf16(float* d, const unsigned a[4],
                                         unsigned b0, unsigned b1) {
    asm volatile("mma.sync.aligned.m16n8k16.row.col.f32.bf16.bf16.f32 "
        "{%0,%1,%2,%3}, {%4,%5,%6,%7}, {%8,%9}, {%0,%1,%2,%3};"
        : "+f"(d[0]), "+f"(d[1]), "+f"(d[2]), "+f"(d[3])
        : "r"(a[0]), "r"(a[1]), "r"(a[2]), "r"(a[3]), "r"(b0), "r"(b1));
}
__device__ __forceinline__ void bsplit(float v, __nv_bfloat16& h, __nv_bfloat16& l) {
    h = __float2bfloat16(v);
    l = __float2bfloat16(v - __bfloat162float(h));
}
// SW128 swizzle within a tile of 128B rows (8 x 16B chunks per row)
__device__ __forceinline__ unsigned swz(int row, int chunk) {
    return (unsigned)(row * 128 + ((chunk ^ (row & 7)) << 4));
}

// ---------------- fused conversion kernels ----------------
struct Split6Args {
    const float*   src[6];
    __nv_bfloat16* hi[6];
    __nv_bfloat16* lo[6];
    int            n4[6];
};

__global__ void split6_kernel(Split6Args a)
{
    const int z = blockIdx.y;
    int i = blockIdx.x * blockDim.x + threadIdx.x;
    if (i >= a.n4[z]) return;
    float4 v = ((const float4*)a.src[z])[i];
    __nv_bfloat162 h0, h1, l0, l1;
    bsplit(v.x, h0.x, l0.x); bsplit(v.y, h0.y, l0.y);
    bsplit(v.z, h1.x, l1.x); bsplit(v.w, h1.y, l1.y);
    ((__nv_bfloat162*)a.hi[z])[2*i]   = h0;
    ((__nv_bfloat162*)a.hi[z])[2*i+1] = h1;
    ((__nv_bfloat162*)a.lo[z])[2*i]   = l0;
    ((__nv_bfloat162*)a.lo[z])[2*i+1] = l1;
}

__global__ void ow_split_kernel(const float* __restrict__ mean,
                                const float* __restrict__ lgstd,
                                const float* __restrict__ eps, int n4)
{
    int i = blockIdx.x * blockDim.x + threadIdx.x;
    if (i >= n4) return;
    float4 m = ((const float4*)mean)[i];
    float4 g = ((const float4*)lgstd)[i];
    float4 e = ((const float4*)eps)[i];
    float4 w = make_float4(m.x + e.x * expf(g.x), m.y + e.y * expf(g.y),
                           m.z + e.z * expf(g.z), m.w + e.w * expf(g.w));
    __nv_bfloat162 h0, h1, l0, l1;
    bsplit(w.x, h0.x, l0.x); bsplit(w.y, h0.y, l0.y);
    bsplit(w.z, h1.x, l1.x); bsplit(w.w, h1.y, l1.y);
    ((__nv_bfloat162*)s_ow_hi)[2*i]   = h0;
    ((__nv_bfloat162*)s_ow_hi)[2*i+1] = h1;
    ((__nv_bfloat162*)s_ow_lo)[2*i]   = l0;
    ((__nv_bfloat162*)s_ow_lo)[2*i+1] = l1;
}

// =====================================================================
// Shared bf16x3 HMMA mainloop (CTA 128x64, BK=64, 8 warps 4x2):
// acc[mi][nj][4] += A*B^T over K, 3 terms Ahi*Bhi + Ahi*Blo + Alo*Bhi.
// 2-stage cp.async double buffer, hi-fragment register pipelining.
// =====================================================================
__device__ __forceinline__ void mma_mainloop(
    const __nv_bfloat16* __restrict__ Ahi, const __nv_bfloat16* __restrict__ Alo,
    const __nv_bfloat16* __restrict__ Bhi_, const __nv_bfloat16* __restrict__ Blo_,
    int lda, int ldb, int K, int blockM, int blockN,
    unsigned sb, float (&acc)[2][4][4])
{
    constexpr int WM = 2, WN = 4;
    constexpr int ABYTES = 128 * 128;
    constexpr int BBYTES = 64 * 128;
    constexpr int BUF = 2 * ABYTES + 2 * BBYTES;  // 48 KB per stage

    const int tid = threadIdx.x;
    const int l   = tid & 31;
    const int w   = tid >> 5;
    const int warp_m = (w & 3) * 32;
    const int warp_n = (w >> 2) * 32;
    const int aq = l >> 3, ar = l & 7;

    const int arow_f = warp_m + ar + 8 * (aq & 1);
    const int acol_f = (aq >> 1);
    const int brow_f = warp_n + ar + 8 * (aq >> 1);
    const int bcol_f = (aq & 1);

    const int NK = K / 64;

    auto load_tile = [&](int kt, int buf) {
        const unsigned tb = sb + buf * BUF;
        #pragma unroll
        for (int t = 0; t < 4; t++) {                  // A: 1024 chunks/matrix
            int i = tid + t * 256;
            int row = i >> 3, c = i & 7;
            size_t g = (size_t)(blockM + row) * lda + (size_t)kt * 64 + c * 8;
            unsigned d = tb + swz(row, c);
            cpasync16(d,          Ahi + g);
            cpasync16(d + ABYTES, Alo + g);
        }
        #pragma unroll
        for (int t = 0; t < 2; t++) {                  // B: 512 chunks/matrix
            int i = tid + t * 256;
            int row = i >> 3, c = i & 7;
            size_t g = (size_t)(blockN + row) * ldb + (size_t)kt * 64 + c * 8;
            unsigned d = tb + 2 * ABYTES + swz(row, c);
            cpasync16(d,          Bhi_ + g);
            cpasync16(d + BBYTES, Blo_ + g);
        }
        CP_COMMIT();
    };

    load_tile(0, 0);

    unsigned ah[2][WM][4], bh[2][WN/2][4];   // hi frags, double buffered
    unsigned al_[WM][4], bl[WN/2][4];        // lo frags, just-in-time

    for (int kt = 0; kt < NK; kt++) {
        CP_WAIT0();
        __syncthreads();
        const unsigned tb = sb + (kt & 1) * BUF;

        // preload ks=0 hi frags
        #pragma unroll
        for (int mi = 0; mi < WM; mi++)
            ldsm4(ah[0][mi], tb + swz(arow_f + mi * 16, acol_f));
        #pragma unroll
        for (int np = 0; np < WN / 2; np++)
            ldsm4(bh[0][np], tb + 2 * ABYTES + swz(brow_f + np * 16, bcol_f));

        if (kt + 1 < NK) load_tile(kt + 1, (kt + 1) & 1);

        #pragma unroll
        for (int ks = 0; ks < 4; ks++) {               // four k16 steps
            const int cur = ks & 1, nxt = cur ^ 1;
            // lo frags for this step (latency hidden by hi*hi MMAs below)
            #pragma unroll
            for (int mi = 0; mi < WM; mi++)
                ldsm4(al_[mi], tb + ABYTES + swz(arow_f + mi * 16, ks * 2 + acol_f));
            #pragma unroll
            for (int np = 0; np < WN / 2; np++)
                ldsm4(bl[np], tb + 2 * ABYTES + BBYTES + swz(brow_f + np * 16, ks * 2 + bcol_f));

            // hi * hi
            #pragma unroll
            for (int mi = 0; mi < WM; mi++)
                #pragma unroll
                for (int nj = 0; nj < WN; nj++) {
                    const unsigned* bhf = &bh[cur][nj >> 1][(nj & 1) * 2];
                    mma_bf16(acc[mi][nj], ah[cur][mi], bhf[0], bhf[1]);
                }

            // prefetch next hi frags
            if (ks < 3) {
                #pragma unroll
                for (int mi = 0; mi < WM; mi++)
                    ldsm4(ah[nxt][mi], tb + swz(arow_f + mi * 16, (ks + 1) * 2 + acol_f));
                #pragma unroll
                for (int np = 0; np < WN / 2; np++)
                    ldsm4(bh[nxt][np], tb + 2 * ABYTES + swz(brow_f + np * 16, (ks + 1) * 2 + bcol_f));
            }

            // cross terms: hi*lo + lo*hi
            #pragma unroll
            for (int mi = 0; mi < WM; mi++)
                #pragma unroll
                for (int nj = 0; nj < WN; nj++) {
                    const unsigned* bhf = &bh[cur][nj >> 1][(nj & 1) * 2];
                    const unsigned* blf = &bl[nj >> 1][(nj & 1) * 2];
                    mma_bf16(acc[mi][nj], ah[cur][mi], blf[0], blf[1]);
                    mma_bf16(acc[mi][nj], al_[mi],     bhf[0], bhf[1]);
                }
        }
    }
}

// =====================================================================
// Fused Q/K/V projection: z=0 Q (scale), z=1 K, z=2 V (transposed layout).
// Scratch arrays referenced as device symbols; only biases are arguments.
// =====================================================================
__global__ __launch_bounds__(256, 2)
void gemm_qkv(const float* __restrict__ q_b, const float* __restrict__ k_b,
              const float* __restrict__ v_b)
{
    extern __shared__ char smem[];
    const unsigned sb = smem_u32(smem);
    const int z = blockIdx.z;

    const __nv_bfloat16 *Ah, *Al, *Bh, *Bl;
    __nv_bfloat16 *Ch, *Cl;
    const float* bias;
    float scale = 1.0f;
    if (z == 0)      { Ah=s_xq_hi; Al=s_xq_lo; Bh=s_wq_hi; Bl=s_wq_lo;
                       Ch=s_q_hi;  Cl=s_q_lo;  bias=q_b;  scale=0.125f; }
    else if (z == 1) { Ah=s_xk_hi; Al=s_xk_lo; Bh=s_wk_hi; Bl=s_wk_lo;
                       Ch=s_k_hi;  Cl=s_k_lo;  bias=k_b; }
    else             { Ah=s_xv_hi; Al=s_xv_lo; Bh=s_wv_hi; Bl=s_wv_lo;
                       Ch=s_v_hi;  Cl=s_v_lo;  bias=v_b; }

    const int blockM = blockIdx.y * 128;
    const int blockN = blockIdx.x * 64;

    float acc[2][4][4];
    #pragma unroll
    for (int i = 0; i < 2; i++)
        #pragma unroll
        for (int j = 0; j < 4; j++)
            #pragma unroll
            for (int r = 0; r < 4; r++) acc[i][j][r] = 0.f;

    mma_mainloop(Ah, Al, Bh, Bl, EMB, EMB, EMB, blockM, blockN, sb, acc);

    const int tid = threadIdx.x, l = tid & 31, w = tid >> 5;
    const int warp_m = (w & 3) * 32, warp_n = (w >> 2) * 32;

    #pragma unroll
    for (int mi = 0; mi < 2; mi++) {
        #pragma unroll
        for (int nj = 0; nj < 4; nj++) {
            float* a = acc[mi][nj];
            const int m0 = blockM + warp_m + mi * 16 + (l >> 2);
            const int n0 = blockN + warp_n + nj * 8 + (l & 3) * 2;
            const float b0 = bias[n0], b1 = bias[n0 + 1];
            const int h = n0 >> 6, d = n0 & 63;
            if (z != 2) {      // Q/K layout [bh][s][d]
                #pragma unroll
                for (int r = 0; r < 2; r++) {
                    const int m = m0 + 8 * r;
                    const int b = m & 1, s = m >> 1;
                    float v0 = (a[2*r]   + b0) * scale;
                    float v1 = (a[2*r+1] + b1) * scale;
                    size_t o = ((size_t)(b * NH + h) * SEQ + s) * HD + d;
                    __nv_bfloat162 hh, ll;
                    bsplit(v0, hh.x, ll.x); bsplit(v1, hh.y, ll.y);
                    *(__nv_bfloat162*)(Ch + o) = hh;
                    *(__nv_bfloat162*)(Cl + o) = ll;
                }
            } else {           // V layout [bh][d][s]
                #pragma unroll
                for (int r = 0; r < 2; r++) {
                    const int m = m0 + 8 * r;
                    const int b = m & 1, s = m >> 1;
                    float v0 = a[2*r]   + b0;
                    float v1 = a[2*r+1] + b1;
                    size_t o0 = ((size_t)(b * NH + h) * HD + d)     * SEQ + s;
                    size_t o1 = ((size_t)(b * NH + h) * HD + d + 1) * SEQ + s;
                    __nv_bfloat16 hh, ll;
                    bsplit(v0, hh, ll); Ch[o0] = hh; Cl[o0] = ll;
                    bsplit(v1, hh, ll); Ch[o1] = hh; Cl[o1] = ll;
                }
            }
        }
    }
}

// =====================================================================
// General GEMM NT. MODE 0: fp32 plain out. MODE 3: ctx split layout.
// =====================================================================
template<int MODE>
__global__ __launch_bounds__(256, 2)
void gemm_mma(const __nv_bfloat16* __restrict__ Ahi, const __nv_bfloat16* __restrict__ Alo,
              const __nv_bfloat16* __restrict__ Bhi_, const __nv_bfloat16* __restrict__ Blo_,
              int lda, int ldb, int K,
              size_t sA, size_t sB, size_t sC,
              float* __restrict__ Cf, int ldc,
              __nv_bfloat16* __restrict__ Chi, __nv_bfloat16* __restrict__ Clo)
{
    extern __shared__ char smem[];
    const unsigned sb = smem_u32(smem);

    const int z = blockIdx.z;
    Ahi  += (size_t)z * sA;  Alo  += (size_t)z * sA;
    Bhi_ += (size_t)z * sB;  Blo_ += (size_t)z * sB;
    const int blockM = blockIdx.y * 128;
    const int blockN = blockIdx.x * 64;

    float acc[2][4][4];
    #pragma unroll
    for (int i = 0; i < 2; i++)
        #pragma unroll
        for (int j = 0; j < 4; j++)
            #pragma unroll
            for (int r = 0; r < 4; r++) acc[i][j][r] = 0.f;

    mma_mainloop(Ahi, Alo, Bhi_, Blo_, lda, ldb, K, blockM, blockN, sb, acc);

    const int tid = threadIdx.x, l = tid & 31, w = tid >> 5;
    const int warp_m = (w & 3) * 32, warp_n = (w >> 2) * 32;

    #pragma unroll
    for (int mi = 0; mi < 2; mi++) {
        #pragma unroll
        for (int nj = 0; nj < 4; nj++) {
            float* a = acc[mi][nj];
            const int m0 = blockM + warp_m + mi * 16 + (l >> 2);
            const int n0 = blockN + warp_n + nj * 8 + (l & 3) * 2;
            if (MODE == 0) {
                float* base = Cf + (size_t)z * sC;
                *(float2*)(base + (size_t)m0 * ldc + n0)       = make_float2(a[0], a[1]);
                *(float2*)(base + (size_t)(m0 + 8) * ldc + n0) = make_float2(a[2], a[3]);
            } else {  // MODE 3: ctx layout
                const int b = z >> 4, h = z & 15;
                #pragma unroll
                for (int r = 0; r < 2; r++) {
                    const int m = m0 + 8 * r;
                    size_t o = ((size_t)m * BSZ + b) * EMB + h * HD + n0;
                    __nv_bfloat162 hh, ll;
                    bsplit(a[2*r],   hh.x, ll.x);
                    bsplit(a[2*r+1], hh.y, ll.y);
                    *(__nv_bfloat162*)(Chi + o) = hh;
                    *(__nv_bfloat162*)(Clo + o) = ll;
                }
            }
        }
    }
}

// ---------------- softmax + head-average + bf16 split ----------------
__device__ __forceinline__ float warpMax(float v) {
    #pragma unroll
    for (int o = 16; o; o >>= 1) v = fmaxf(v, __shfl_xor_sync(0xffffffffu, v, o));
    return v;
}
__device__ __forceinline__ float warpSum(float v) {
    #pragma unroll
    for (int o = 16; o; o >>= 1) v += __shfl_xor_sync(0xffffffffu, v, o);
    return v;
}

__global__ void softmax_avg_kernel(const float* __restrict__ attn,
                                   float* __restrict__ avg)
{
    __shared__ float redM[8], redS[8];
    const int bq = blockIdx.x;
    const int b = bq >> 11;          // SEQ = 2048
    const int q = bq & 2047;
    const int tid = threadIdx.x, lane = tid & 31, wid = tid >> 5;

    float4 a0 = make_float4(0.f, 0.f, 0.f, 0.f);
    float4 a1 = make_float4(0.f, 0.f, 0.f, 0.f);

    // prefetch head 0
    const size_t row0 = ((size_t)(b * NH) * SEQ + q) * SEQ;
    float4 c0 = ((const float4*)(attn + row0))[tid];
    float4 c1 = ((const float4*)(attn + row0))[tid + 256];

    for (int h = 0; h < NH; h++) {
        const size_t rowoff = ((size_t)(b * NH + h) * SEQ + q) * SEQ;
        // prefetch next head's rows (in flight across both barriers)
        float4 n0, n1;
        if (h + 1 < NH) {
            const size_t nxt = rowoff + (size_t)SEQ * SEQ;
            n0 = ((const float4*)(attn + nxt))[tid];
            n1 = ((const float4*)(attn + nxt))[tid + 256];
        }

        // ---- max phase (1 barrier) ----
        float mx = fmaxf(fmaxf(fmaxf(c0.x, c0.y), fmaxf(c0.z, c0.w)),
                         fmaxf(fmaxf(c1.x, c1.y), fmaxf(c1.z, c1.w)));
        mx = warpMax(mx);
        if (lane == 0) redM[wid] = mx;
        __syncthreads();
        float rowMax = redM[0];
        #pragma unroll
        for (int i = 1; i < 8; i++) rowMax = fmaxf(rowMax, redM[i]);

        // ---- exp + sum phase (1 barrier) ----
        c0.x = __expf(c0.x - rowMax); c0.y = __expf(c0.y - rowMax);
        c0.z = __expf(c0.z - rowMax); c0.w = __expf(c0.w - rowMax);
        c1.x = __expf(c1.x - rowMax); c1.y = __expf(c1.y - rowMax);
        c1.z = __expf(c1.z - rowMax); c1.w = __expf(c1.w - rowMax);
        float sv = c0.x + c0.y + c0.z + c0.w + c1.x + c1.y + c1.z + c1.w;
        sv = warpSum(sv);
        if (lane == 0) redS[wid] = sv;
        __syncthreads();
        float rs = redS[0];
        #pragma unroll
        for (int i = 1; i < 8; i++) rs += redS[i];
        const float inv = 1.f / rs;

        c0.x *= inv; c0.y *= inv; c0.z *= inv; c0.w *= inv;
        c1.x *= inv; c1.y *= inv; c1.z *= inv; c1.w *= inv;

        __nv_bfloat162* ph2 = (__nv_bfloat162*)(s_p_hi + rowoff);
        __nv_bfloat162* pl2 = (__nv_bfloat162*)(s_p_lo + rowoff);
        __nv_bfloat162 h0, h1, l0, l1;
        bsplit(c0.x, h0.x, l0.x); bsplit(c0.y, h0.y, l0.y);
        bsplit(c0.z, h1.x, l1.x); bsplit(c0.w, h1.y, l1.y);
        ph2[2*tid] = h0; ph2[2*tid+1] = h1;
        pl2[2*tid] = l0; pl2[2*tid+1] = l1;
        bsplit(c1.x, h0.x, l0.x); bsplit(c1.y, h0.y, l0.y);
        bsplit(c1.z, h1.x, l1.x); bsplit(c1.w, h1.y, l1.y);
        ph2[2*(tid+256)] = h0; ph2[2*(tid+256)+1] = h1;
        pl2[2*(tid+256)] = l0; pl2[2*(tid+256)+1] = l1;

        a0.x += c0.x; a0.y += c0.y; a0.z += c0.z; a0.w += c0.w;
        a1.x += c1.x; a1.y += c1.y; a1.z += c1.z; a1.w += c1.w;

        c0 = n0; c1 = n1;
    }

    const float invH = 1.f / NH;
    a0.x *= invH; a0.y *= invH; a0.z *= invH; a0.w *= invH;
    a1.x *= invH; a1.y *= invH; a1.z *= invH; a1.w *= invH;
    float4* o4 = (float4*)(avg + ((size_t)b * SEQ + q) * SEQ);
    o4[tid]       = a0;
    o4[tid + 256] = a1;
}

// ---------------- launch ----------------
extern "C" void kernel_launch(void* const* d_in, const int* in_sizes, int n_in,
                              void* d_out, int out_size)
{
    const float* query   = (const float*)d_in[0];
    const float* key     = (const float*)d_in[1];
    const float* value   = (const float*)d_in[2];
    const float* q_w     = (const float*)d_in[3];
    const float* q_b     = (const float*)d_in[4];
    const float* k_w     = (const float*)d_in[5];
    const float* k_b     = (const float*)d_in[6];
    const float* v_w     = (const float*)d_in[7];
    const float* v_b     = (const float*)d_in[8];
    const float* ow_mean = (const float*)d_in[9];
    const float* ow_lg   = (const float*)d_in[10];
    const float* eps     = (const float*)d_in[11];

    float* out_main = (float*)d_out;
    float* out_avg  = out_main + (size_t)MROWS * EMB;

    __nv_bfloat16 *xqh,*xql,*xkh,*xkl,*xvh,*xvl,*wqh,*wql,*wkh,*wkl,*wvh,*wvl;
    __nv_bfloat16 *owh,*owl,*qh,*ql,*kh,*kl,*vh,*vl,*pph,*ppl,*ch,*cl;
    float* attn_p;
    cudaGetSymbolAddress((void**)&xqh, s_xq_hi); cudaGetSymbolAddress((void**)&xql, s_xq_lo);
    cudaGetSymbolAddress((void**)&xkh, s_xk_hi); cudaGetSymbolAddress((void**)&xkl, s_xk_lo);
    cudaGetSymbolAddress((void**)&xvh, s_xv_hi); cudaGetSymbolAddress((void**)&xvl, s_xv_lo);
    cudaGetSymbolAddress((void**)&wqh, s_wq_hi); cudaGetSymbolAddress((void**)&wql, s_wq_lo);
    cudaGetSymbolAddress((void**)&wkh, s_wk_hi); cudaGetSymbolAddress((void**)&wkl, s_wk_lo);
    cudaGetSymbolAddress((void**)&wvh, s_wv_hi); cudaGetSymbolAddress((void**)&wvl, s_wv_lo);
    cudaGetSymbolAddress((void**)&owh, s_ow_hi); cudaGetSymbolAddress((void**)&owl, s_ow_lo);
    cudaGetSymbolAddress((void**)&qh,  s_q_hi);  cudaGetSymbolAddress((void**)&ql,  s_q_lo);
    cudaGetSymbolAddress((void**)&kh,  s_k_hi);  cudaGetSymbolAddress((void**)&kl,  s_k_lo);
    cudaGetSymbolAddress((void**)&vh,  s_v_hi);  cudaGetSymbolAddress((void**)&vl,  s_v_lo);
    cudaGetSymbolAddress((void**)&pph, s_p_hi);  cudaGetSymbolAddress((void**)&ppl, s_p_lo);
    cudaGetSymbolAddress((void**)&ch,  s_c_hi);  cudaGetSymbolAddress((void**)&cl,  s_c_lo);
    cudaGetSymbolAddress((void**)&attn_p, g_attn);

    // dynamic smem: 2 stages x 48 KB = 96 KB per CTA (2 CTAs/SM)
    const int SMEM = 2 * (2 * 128 * 128 + 2 * 64 * 128);
    cudaFuncSetAttribute(gemm_qkv,    cudaFuncAttributeMaxDynamicSharedMemorySize, SMEM);
    cudaFuncSetAttribute(gemm_mma<0>, cudaFuncAttributeMaxDynamicSharedMemorySize, SMEM);
    cudaFuncSetAttribute(gemm_mma<3>, cudaFuncAttributeMaxDynamicSharedMemorySize, SMEM);

    // 1. fused split (launch #1), sampled output weight (launch #2)
    const int nx4 = MROWS * EMB / 4, nw4 = EMB * EMB / 4;
    {
        Split6Args a;
        a.src[0]=query; a.src[1]=key; a.src[2]=value;
        a.src[3]=q_w;   a.src[4]=k_w; a.src[5]=v_w;
        a.hi[0]=xqh; a.hi[1]=xkh; a.hi[2]=xvh; a.hi[3]=wqh; a.hi[4]=wkh; a.hi[5]=wvh;
        a.lo[0]=xql; a.lo[1]=xkl; a.lo[2]=xvl; a.lo[3]=wql; a.lo[4]=wkl; a.lo[5]=wvl;
        a.n4[0]=a.n4[1]=a.n4[2]=nx4; a.n4[3]=a.n4[4]=a.n4[5]=nw4;
        split6_kernel<<<dim3((nx4 + 255)/256, 6), 256>>>(a);
        ow_split_kernel<<<(nw4 + 255)/256, 256>>>(ow_mean, ow_lg, eps, nw4);
    }

    // 2. fused Q/K/V projections (launch #3)
    const dim3 gQKV(EMB/64, MROWS/128, 3);
    gemm_qkv<<<gQKV, 256, SMEM>>>(q_b, k_b, v_b);

    // 3. scores = Q K^T (launch #4)
    const dim3 gScore(SEQ/64, SEQ/128, BH);
    gemm_mma<0><<<gScore, 256, SMEM>>>(qh, ql, kh, kl, HD, HD, HD,
                                       (size_t)SEQ*HD, (size_t)SEQ*HD,
                                       (size_t)SEQ*SEQ, attn_p, SEQ,
                                       nullptr, nullptr);

    // 4. softmax + avg + bf16 split of probs (launch #5)
    softmax_avg_kernel<<<BSZ*SEQ, 256>>>(attn_p, out_avg);

    // 5. ctx = P @ V (launch #6 — ncu captures this one)
    const dim3 gCtx(1, SEQ/128, BH);
    gemm_mma<3><<<gCtx, 256, SMEM>>>(pph, ppl, vh, vl, SEQ, SEQ, SEQ,
                                     (size_t)SEQ*SEQ, (size_t)HD*SEQ, 0,
                                     nullptr, 0, ch, cl);

    // 6. out = ctx @ o_w^T  (fp32 out)
    const dim3 gOut(EMB/64, MROWS/128, 1);
    gemm_mma<0><<<gOut, 256, SMEM>>>(ch, cl, owh, owl, EMB, EMB, EMB,
                                     0, 0, 0, out_main, EMB,
                                     nullptr, nullptr);
}

// round 10
// speedup vs baseline: 1.1588x; 1.0187x over previous
#include <cuda_runtime.h>
#include <cuda_bf16.h>
#include <math.h>
#include <float.h>

// ---------------- problem constants ----------------
#define SEQ  2048
#define BSZ  2
#define EMB  1024
#define NH   16
#define HD   64
#define BH   (BSZ*NH)          // 32
#define MROWS (SEQ*BSZ)        // 4096

// ---------------- scratch (static device arrays) ----------------
__device__ __align__(1024) __nv_bfloat16 s_xq_hi[(size_t)MROWS*EMB];
__device__ __align__(1024) __nv_bfloat16 s_xq_lo[(size_t)MROWS*EMB];
__device__ __align__(1024) __nv_bfloat16 s_xk_hi[(size_t)MROWS*EMB];
__device__ __align__(1024) __nv_bfloat16 s_xk_lo[(size_t)MROWS*EMB];
__device__ __align__(1024) __nv_bfloat16 s_xv_hi[(size_t)MROWS*EMB];
__device__ __align__(1024) __nv_bfloat16 s_xv_lo[(size_t)MROWS*EMB];
__device__ __align__(1024) __nv_bfloat16 s_wq_hi[(size_t)EMB*EMB];
__device__ __align__(1024) __nv_bfloat16 s_wq_lo[(size_t)EMB*EMB];
__device__ __align__(1024) __nv_bfloat16 s_wk_hi[(size_t)EMB*EMB];
__device__ __align__(1024) __nv_bfloat16 s_wk_lo[(size_t)EMB*EMB];
__device__ __align__(1024) __nv_bfloat16 s_wv_hi[(size_t)EMB*EMB];
__device__ __align__(1024) __nv_bfloat16 s_wv_lo[(size_t)EMB*EMB];
__device__ __align__(1024) __nv_bfloat16 s_ow_hi[(size_t)EMB*EMB];
__device__ __align__(1024) __nv_bfloat16 s_ow_lo[(size_t)EMB*EMB];
__device__ __align__(1024) __nv_bfloat16 s_q_hi[(size_t)BH*SEQ*HD];
__device__ __align__(1024) __nv_bfloat16 s_q_lo[(size_t)BH*SEQ*HD];
__device__ __align__(1024) __nv_bfloat16 s_k_hi[(size_t)BH*SEQ*HD];
__device__ __align__(1024) __nv_bfloat16 s_k_lo[(size_t)BH*SEQ*HD];
__device__ __align__(1024) __nv_bfloat16 s_v_hi[(size_t)BH*HD*SEQ];  // [bh][d][s]
__device__ __align__(1024) __nv_bfloat16 s_v_lo[(size_t)BH*HD*SEQ];
__device__ __align__(1024) float         g_attn[(size_t)BH*SEQ*SEQ]; // 512 MB
__device__ __align__(1024) __nv_bfloat16 s_p_hi[(size_t)BH*SEQ*SEQ]; // 256 MB
__device__ __align__(1024) __nv_bfloat16 s_p_lo[(size_t)BH*SEQ*SEQ]; // 256 MB
__device__ __align__(1024) __nv_bfloat16 s_c_hi[(size_t)MROWS*EMB];
__device__ __align__(1024) __nv_bfloat16 s_c_lo[(size_t)MROWS*EMB];

// ---------------- PTX helpers ----------------
__device__ __forceinline__ unsigned smem_u32(const void* p) {
    unsigned a;
    asm("{ .reg .u64 t; cvta.to.shared.u64 t, %1; cvt.u32.u64 %0, t; }"
        : "=r"(a) : "l"(p));
    return a;
}
__device__ __forceinline__ void cpasync16(unsigned dst, const void* src) {
    asm volatile("cp.async.cg.shared.global [%0], [%1], 16;" :: "r"(dst), "l"(src));
}
#define CP_COMMIT() asm volatile("cp.async.commit_group;" ::: "memory")
#define CP_WAIT0()  asm volatile("cp.async.wait_group 0;" ::: "memory")
#define CP_WAIT1()  asm volatile("cp.async.wait_group 1;" ::: "memory")

__device__ __forceinline__ void ldsm4(unsigned r[4], unsigned addr) {
    asm volatile("ldmatrix.sync.aligned.m8n8.x4.shared.b16 {%0,%1,%2,%3}, [%4];"
        : "=r"(r[0]), "=r"(r[1]), "=r"(r[2]), "=r"(r[3]) : "r"(addr));
}
__device__ __forceinline__ void mma_bf16(float* d, const unsigned a[4],
                                         unsigned b0, unsigned b1) {
    asm volatile("mma.sync.aligned.m16n8k16.row.col.f32.bf16.bf16.f32 "
        "{%0,%1,%2,%3}, {%4,%5,%6,%7}, {%8,%9}, {%0,%1,%2,%3};"
        : "+f"(d[0]), "+f"(d[1]), "+f"(d[2]), "+f"(d[3])
        : "r"(a[0]), "r"(a[1]), "r"(a[2]), "r"(a[3]), "r"(b0), "r"(b1));
}
__device__ __forceinline__ void bsplit(float v, __nv_bfloat16& h, __nv_bfloat16& l) {
    h = __float2bfloat16(v);
    l = __float2bfloat16(v - __bfloat162float(h));
}
// SW128 swizzle within a tile of 128B rows (8 x 16B chunks per row)
__device__ __forceinline__ unsigned swz(int row, int chunk) {
    return (unsigned)(row * 128 + ((chunk ^ (row & 7)) << 4));
}

// ---------------- fused conversion kernels ----------------
struct Split6Args {
    const float*   src[6];
    __nv_bfloat16* hi[6];
    __nv_bfloat16* lo[6];
    int            n4[6];
};

__global__ void split6_kernel(Split6Args a)
{
    const int z = blockIdx.y;
    int i = blockIdx.x * blockDim.x + threadIdx.x;
    if (i >= a.n4[z]) return;
    float4 v = ((const float4*)a.src[z])[i];
    __nv_bfloat162 h0, h1, l0, l1;
    bsplit(v.x, h0.x, l0.x); bsplit(v.y, h0.y, l0.y);
    bsplit(v.z, h1.x, l1.x); bsplit(v.w, h1.y, l1.y);
    ((__nv_bfloat162*)a.hi[z])[2*i]   = h0;
    ((__nv_bfloat162*)a.hi[z])[2*i+1] = h1;
    ((__nv_bfloat162*)a.lo[z])[2*i]   = l0;
    ((__nv_bfloat162*)a.lo[z])[2*i+1] = l1;
}

__global__ void ow_split_kernel(const float* __restrict__ mean,
                                const float* __restrict__ lgstd,
                                const float* __restrict__ eps, int n4)
{
    int i = blockIdx.x * blockDim.x + threadIdx.x;
    if (i >= n4) return;
    float4 m = ((const float4*)mean)[i];
    float4 g = ((const float4*)lgstd)[i];
    float4 e = ((const float4*)eps)[i];
    float4 w = make_float4(m.x + e.x * expf(g.x), m.y + e.y * expf(g.y),
                           m.z + e.z * expf(g.z), m.w + e.w * expf(g.w));
    __nv_bfloat162 h0, h1, l0, l1;
    bsplit(w.x, h0.x, l0.x); bsplit(w.y, h0.y, l0.y);
    bsplit(w.z, h1.x, l1.x); bsplit(w.w, h1.y, l1.y);
    ((__nv_bfloat162*)s_ow_hi)[2*i]   = h0;
    ((__nv_bfloat162*)s_ow_hi)[2*i+1] = h1;
    ((__nv_bfloat162*)s_ow_lo)[2*i]   = l0;
    ((__nv_bfloat162*)s_ow_lo)[2*i+1] = l1;
}

// =====================================================================
// Shared bf16x3 HMMA mainloop (CTA 128x64, BK=64, 8 warps 4x2):
// acc[mi][nj][4] += A*B^T over K, 3 terms Ahi*Bhi + Ahi*Blo + Alo*Bhi.
// 2-stage cp.async double buffer, hi-fragment register pipelining.
// =====================================================================
__device__ __forceinline__ void mma_mainloop(
    const __nv_bfloat16* __restrict__ Ahi, const __nv_bfloat16* __restrict__ Alo,
    const __nv_bfloat16* __restrict__ Bhi_, const __nv_bfloat16* __restrict__ Blo_,
    int lda, int ldb, int K, int blockM, int blockN,
    unsigned sb, float (&acc)[2][4][4])
{
    constexpr int WM = 2, WN = 4;
    constexpr int ABYTES = 128 * 128;
    constexpr int BBYTES = 64 * 128;
    constexpr int BUF = 2 * ABYTES + 2 * BBYTES;  // 48 KB per stage

    const int tid = threadIdx.x;
    const int l   = tid & 31;
    const int w   = tid >> 5;
    const int warp_m = (w & 3) * 32;
    const int warp_n = (w >> 2) * 32;
    const int aq = l >> 3, ar = l & 7;

    const int arow_f = warp_m + ar + 8 * (aq & 1);
    const int acol_f = (aq >> 1);
    const int brow_f = warp_n + ar + 8 * (aq >> 1);
    const int bcol_f = (aq & 1);

    const int NK = K / 64;

    auto load_tile = [&](int kt, int buf) {
        const unsigned tb = sb + buf * BUF;
        #pragma unroll
        for (int t = 0; t < 4; t++) {                  // A: 1024 chunks/matrix
            int i = tid + t * 256;
            int row = i >> 3, c = i & 7;
            size_t g = (size_t)(blockM + row) * lda + (size_t)kt * 64 + c * 8;
            unsigned d = tb + swz(row, c);
            cpasync16(d,          Ahi + g);
            cpasync16(d + ABYTES, Alo + g);
        }
        #pragma unroll
        for (int t = 0; t < 2; t++) {                  // B: 512 chunks/matrix
            int i = tid + t * 256;
            int row = i >> 3, c = i & 7;
            size_t g = (size_t)(blockN + row) * ldb + (size_t)kt * 64 + c * 8;
            unsigned d = tb + 2 * ABYTES + swz(row, c);
            cpasync16(d,          Bhi_ + g);
            cpasync16(d + BBYTES, Blo_ + g);
        }
        CP_COMMIT();
    };

    load_tile(0, 0);

    unsigned ah[2][WM][4], bh[2][WN/2][4];   // hi frags, double buffered
    unsigned al_[WM][4], bl[WN/2][4];        // lo frags, just-in-time

    for (int kt = 0; kt < NK; kt++) {
        CP_WAIT0();
        __syncthreads();
        const unsigned tb = sb + (kt & 1) * BUF;

        // preload ks=0 hi frags
        #pragma unroll
        for (int mi = 0; mi < WM; mi++)
            ldsm4(ah[0][mi], tb + swz(arow_f + mi * 16, acol_f));
        #pragma unroll
        for (int np = 0; np < WN / 2; np++)
            ldsm4(bh[0][np], tb + 2 * ABYTES + swz(brow_f + np * 16, bcol_f));

        if (kt + 1 < NK) load_tile(kt + 1, (kt + 1) & 1);

        #pragma unroll
        for (int ks = 0; ks < 4; ks++) {               // four k16 steps
            const int cur = ks & 1, nxt = cur ^ 1;
            // lo frags for this step (latency hidden by hi*hi MMAs below)
            #pragma unroll
            for (int mi = 0; mi < WM; mi++)
                ldsm4(al_[mi], tb + ABYTES + swz(arow_f + mi * 16, ks * 2 + acol_f));
            #pragma unroll
            for (int np = 0; np < WN / 2; np++)
                ldsm4(bl[np], tb + 2 * ABYTES + BBYTES + swz(brow_f + np * 16, ks * 2 + bcol_f));

            // hi * hi
            #pragma unroll
            for (int mi = 0; mi < WM; mi++)
                #pragma unroll
                for (int nj = 0; nj < WN; nj++) {
                    const unsigned* bhf = &bh[cur][nj >> 1][(nj & 1) * 2];
                    mma_bf16(acc[mi][nj], ah[cur][mi], bhf[0], bhf[1]);
                }

            // prefetch next hi frags
            if (ks < 3) {
                #pragma unroll
                for (int mi = 0; mi < WM; mi++)
                    ldsm4(ah[nxt][mi], tb + swz(arow_f + mi * 16, (ks + 1) * 2 + acol_f));
                #pragma unroll
                for (int np = 0; np < WN / 2; np++)
                    ldsm4(bh[nxt][np], tb + 2 * ABYTES + swz(brow_f + np * 16, (ks + 1) * 2 + bcol_f));
            }

            // cross terms: hi*lo + lo*hi
            #pragma unroll
            for (int mi = 0; mi < WM; mi++)
                #pragma unroll
                for (int nj = 0; nj < WN; nj++) {
                    const unsigned* bhf = &bh[cur][nj >> 1][(nj & 1) * 2];
                    const unsigned* blf = &bl[nj >> 1][(nj & 1) * 2];
                    mma_bf16(acc[mi][nj], ah[cur][mi], blf[0], blf[1]);
                    mma_bf16(acc[mi][nj], al_[mi],     bhf[0], bhf[1]);
                }
        }
    }
}

// =====================================================================
// Fused Q/K/V projection: z=0 Q (scale), z=1 K, z=2 V (transposed layout).
// =====================================================================
__global__ __launch_bounds__(256, 2)
void gemm_qkv(const float* __restrict__ q_b, const float* __restrict__ k_b,
              const float* __restrict__ v_b)
{
    extern __shared__ char smem[];
    const unsigned sb = smem_u32(smem);
    const int z = blockIdx.z;

    const __nv_bfloat16 *Ah, *Al, *Bh, *Bl;
    __nv_bfloat16 *Ch, *Cl;
    const float* bias;
    float scale = 1.0f;
    if (z == 0)      { Ah=s_xq_hi; Al=s_xq_lo; Bh=s_wq_hi; Bl=s_wq_lo;
                       Ch=s_q_hi;  Cl=s_q_lo;  bias=q_b;  scale=0.125f; }
    else if (z == 1) { Ah=s_xk_hi; Al=s_xk_lo; Bh=s_wk_hi; Bl=s_wk_lo;
                       Ch=s_k_hi;  Cl=s_k_lo;  bias=k_b; }
    else             { Ah=s_xv_hi; Al=s_xv_lo; Bh=s_wv_hi; Bl=s_wv_lo;
                       Ch=s_v_hi;  Cl=s_v_lo;  bias=v_b; }

    const int blockM = blockIdx.y * 128;
    const int blockN = blockIdx.x * 64;

    float acc[2][4][4];
    #pragma unroll
    for (int i = 0; i < 2; i++)
        #pragma unroll
        for (int j = 0; j < 4; j++)
            #pragma unroll
            for (int r = 0; r < 4; r++) acc[i][j][r] = 0.f;

    mma_mainloop(Ah, Al, Bh, Bl, EMB, EMB, EMB, blockM, blockN, sb, acc);

    const int tid = threadIdx.x, l = tid & 31, w = tid >> 5;
    const int warp_m = (w & 3) * 32, warp_n = (w >> 2) * 32;

    #pragma unroll
    for (int mi = 0; mi < 2; mi++) {
        #pragma unroll
        for (int nj = 0; nj < 4; nj++) {
            float* a = acc[mi][nj];
            const int m0 = blockM + warp_m + mi * 16 + (l >> 2);
            const int n0 = blockN + warp_n + nj * 8 + (l & 3) * 2;
            const float b0 = bias[n0], b1 = bias[n0 + 1];
            const int h = n0 >> 6, d = n0 & 63;
            if (z != 2) {      // Q/K layout [bh][s][d]
                #pragma unroll
                for (int r = 0; r < 2; r++) {
                    const int m = m0 + 8 * r;
                    const int b = m & 1, s = m >> 1;
                    float v0 = (a[2*r]   + b0) * scale;
                    float v1 = (a[2*r+1] + b1) * scale;
                    size_t o = ((size_t)(b * NH + h) * SEQ + s) * HD + d;
                    __nv_bfloat162 hh, ll;
                    bsplit(v0, hh.x, ll.x); bsplit(v1, hh.y, ll.y);
                    *(__nv_bfloat162*)(Ch + o) = hh;
                    *(__nv_bfloat162*)(Cl + o) = ll;
                }
            } else {           // V layout [bh][d][s]
                #pragma unroll
                for (int r = 0; r < 2; r++) {
                    const int m = m0 + 8 * r;
                    const int b = m & 1, s = m >> 1;
                    float v0 = a[2*r]   + b0;
                    float v1 = a[2*r+1] + b1;
                    size_t o0 = ((size_t)(b * NH + h) * HD + d)     * SEQ + s;
                    size_t o1 = ((size_t)(b * NH + h) * HD + d + 1) * SEQ + s;
                    __nv_bfloat16 hh, ll;
                    bsplit(v0, hh, ll); Ch[o0] = hh; Cl[o0] = ll;
                    bsplit(v1, hh, ll); Ch[o1] = hh; Cl[o1] = ll;
                }
            }
        }
    }
}

// =====================================================================
// Streaming scores GEMM: D[q,k] = Q[q,:] . K[k,:]  per bh.
// Q tile (128 x 64 hi/lo) resident; K tiles streamed via 3-slot ring.
// grid (1, SEQ/128, BH). Writes fp32 attn directly per n-block.
// =====================================================================
__global__ __launch_bounds__(256, 2)
void gemm_score(const __nv_bfloat16* __restrict__ Qh, const __nv_bfloat16* __restrict__ Ql,
                const __nv_bfloat16* __restrict__ Kh, const __nv_bfloat16* __restrict__ Kl,
                float* __restrict__ D)
{
    constexpr int AB = 128 * 128;   // 16 KB per A matrix
    constexpr int BB = 64 * 128;    // 8 KB per B matrix
    constexpr int NB = SEQ / 64;    // 32 n-blocks

    extern __shared__ char smem[];
    const unsigned sb = smem_u32(smem);
    const unsigned bbase = sb + 2 * AB;     // B ring: slot s at bbase + s*2*BB

    const int tid = threadIdx.x, l = tid & 31, w = tid >> 5;
    const int warp_m = (w & 3) * 32, warp_n = (w >> 2) * 32;
    const int aq = l >> 3, ar = l & 7;
    const int arow_f = warp_m + ar + 8 * (aq & 1);
    const int acol_f = (aq >> 1);
    const int brow_f = warp_n + ar + 8 * (aq >> 1);
    const int bcol_f = (aq & 1);

    const int z = blockIdx.z;
    const int blockM = blockIdx.y * 128;
    Qh += (size_t)z * SEQ * HD;  Ql += (size_t)z * SEQ * HD;
    Kh += (size_t)z * SEQ * HD;  Kl += (size_t)z * SEQ * HD;
    D  += (size_t)z * SEQ * SEQ;

    auto load_b = [&](int nb) {
        const unsigned tb = bbase + (nb % 3) * (2 * BB);
        #pragma unroll
        for (int t = 0; t < 2; t++) {
            int i = tid + t * 256;
            int row = i >> 3, c = i & 7;
            size_t g = (size_t)(nb * 64 + row) * HD + c * 8;
            unsigned d = tb + swz(row, c);
            cpasync16(d,      Kh + g);
            cpasync16(d + BB, Kl + g);
        }
        CP_COMMIT();
    };

    // A (Q tile) + B0 in group 0
    {
        #pragma unroll
        for (int t = 0; t < 4; t++) {
            int i = tid + t * 256;
            int row = i >> 3, c = i & 7;
            size_t g = (size_t)(blockM + row) * HD + c * 8;
            unsigned d = sb + swz(row, c);
            cpasync16(d,      Qh + g);
            cpasync16(d + AB, Ql + g);
        }
        const unsigned tb = bbase;
        #pragma unroll
        for (int t = 0; t < 2; t++) {
            int i = tid + t * 256;
            int row = i >> 3, c = i & 7;
            size_t g = (size_t)(row) * HD + c * 8;
            unsigned d = tb + swz(row, c);
            cpasync16(d,      Kh + g);
            cpasync16(d + BB, Kl + g);
        }
        CP_COMMIT();
    }
    load_b(1);

    unsigned ah[2][2][4], bh[2][2][4];   // hi frags, double buffered over ks
    unsigned al_[2][4], bl[2][4];        // lo frags, just-in-time

    for (int nb = 0; nb < NB; nb++) {
        if (nb + 1 < NB) { CP_WAIT1(); } else { CP_WAIT0(); }
        __syncthreads();
        if (nb + 2 < NB) load_b(nb + 2);

        const unsigned btile = bbase + (nb % 3) * (2 * BB);

        float acc[2][4][4];
        #pragma unroll
        for (int i = 0; i < 2; i++)
            #pragma unroll
            for (int j = 0; j < 4; j++)
                #pragma unroll
                for (int r = 0; r < 4; r++) acc[i][j][r] = 0.f;

        // preload ks=0 hi frags
        #pragma unroll
        for (int mi = 0; mi < 2; mi++)
            ldsm4(ah[0][mi], sb + swz(arow_f + mi * 16, acol_f));
        #pragma unroll
        for (int np = 0; np < 2; np++)
            ldsm4(bh[0][np], btile + swz(brow_f + np * 16, bcol_f));

        #pragma unroll
        for (int ks = 0; ks < 4; ks++) {
            const int cur = ks & 1, nxt = cur ^ 1;
            #pragma unroll
            for (int mi = 0; mi < 2; mi++)
                ldsm4(al_[mi], sb + AB + swz(arow_f + mi * 16, ks * 2 + acol_f));
            #pragma unroll
            for (int np = 0; np < 2; np++)
                ldsm4(bl[np], btile + BB + swz(brow_f + np * 16, ks * 2 + bcol_f));

            #pragma unroll
            for (int mi = 0; mi < 2; mi++)
                #pragma unroll
                for (int nj = 0; nj < 4; nj++) {
                    const unsigned* bhf = &bh[cur][nj >> 1][(nj & 1) * 2];
                    mma_bf16(acc[mi][nj], ah[cur][mi], bhf[0], bhf[1]);
                }

            if (ks < 3) {
                #pragma unroll
                for (int mi = 0; mi < 2; mi++)
                    ldsm4(ah[nxt][mi], sb + swz(arow_f + mi * 16, (ks + 1) * 2 + acol_f));
                #pragma unroll
                for (int np = 0; np < 2; np++)
                    ldsm4(bh[nxt][np], btile + swz(brow_f + np * 16, (ks + 1) * 2 + bcol_f));
            }

            #pragma unroll
            for (int mi = 0; mi < 2; mi++)
                #pragma unroll
                for (int nj = 0; nj < 4; nj++) {
                    const unsigned* bhf = &bh[cur][nj >> 1][(nj & 1) * 2];
                    const unsigned* blf = &bl[nj >> 1][(nj & 1) * 2];
                    mma_bf16(acc[mi][nj], ah[cur][mi], blf[0], blf[1]);
                    mma_bf16(acc[mi][nj], al_[mi],     bhf[0], bhf[1]);
                }
        }

        // epilogue: write this 128x64 fp32 block
        #pragma unroll
        for (int mi = 0; mi < 2; mi++)
            #pragma unroll
            for (int nj = 0; nj < 4; nj++) {
                float* a = acc[mi][nj];
                const int m0 = blockM + warp_m + mi * 16 + (l >> 2);
                const int n0 = nb * 64 + warp_n + nj * 8 + (l & 3) * 2;
                *(float2*)(D + (size_t)m0 * SEQ + n0)       = make_float2(a[0], a[1]);
                *(float2*)(D + (size_t)(m0 + 8) * SEQ + n0) = make_float2(a[2], a[3]);
            }
    }
}

// =====================================================================
// General GEMM NT. MODE 0: fp32 plain out. MODE 3: ctx split layout.
// =====================================================================
template<int MODE>
__global__ __launch_bounds__(256, 2)
void gemm_mma(const __nv_bfloat16* __restrict__ Ahi, const __nv_bfloat16* __restrict__ Alo,
              const __nv_bfloat16* __restrict__ Bhi_, const __nv_bfloat16* __restrict__ Blo_,
              int lda, int ldb, int K,
              size_t sA, size_t sB, size_t sC,
              float* __restrict__ Cf, int ldc,
              __nv_bfloat16* __restrict__ Chi, __nv_bfloat16* __restrict__ Clo)
{
    extern __shared__ char smem[];
    const unsigned sb = smem_u32(smem);

    const int z = blockIdx.z;
    Ahi  += (size_t)z * sA;  Alo  += (size_t)z * sA;
    Bhi_ += (size_t)z * sB;  Blo_ += (size_t)z * sB;
    const int blockM = blockIdx.y * 128;
    const int blockN = blockIdx.x * 64;

    float acc[2][4][4];
    #pragma unroll
    for (int i = 0; i < 2; i++)
        #pragma unroll
        for (int j = 0; j < 4; j++)
            #pragma unroll
            for (int r = 0; r < 4; r++) acc[i][j][r] = 0.f;

    mma_mainloop(Ahi, Alo, Bhi_, Blo_, lda, ldb, K, blockM, blockN, sb, acc);

    const int tid = threadIdx.x, l = tid & 31, w = tid >> 5;
    const int warp_m = (w & 3) * 32, warp_n = (w >> 2) * 32;

    #pragma unroll
    for (int mi = 0; mi < 2; mi++) {
        #pragma unroll
        for (int nj = 0; nj < 4; nj++) {
            float* a = acc[mi][nj];
            const int m0 = blockM + warp_m + mi * 16 + (l >> 2);
            const int n0 = blockN + warp_n + nj * 8 + (l & 3) * 2;
            if (MODE == 0) {
                float* base = Cf + (size_t)z * sC;
                *(float2*)(base + (size_t)m0 * ldc + n0)       = make_float2(a[0], a[1]);
                *(float2*)(base + (size_t)(m0 + 8) * ldc + n0) = make_float2(a[2], a[3]);
            } else {  // MODE 3: ctx layout
                const int b = z >> 4, h = z & 15;
                #pragma unroll
                for (int r = 0; r < 2; r++) {
                    const int m = m0 + 8 * r;
                    size_t o = ((size_t)m * BSZ + b) * EMB + h * HD + n0;
                    __nv_bfloat162 hh, ll;
                    bsplit(a[2*r],   hh.x, ll.x);
                    bsplit(a[2*r+1], hh.y, ll.y);
                    *(__nv_bfloat162*)(Chi + o) = hh;
                    *(__nv_bfloat162*)(Clo + o) = ll;
                }
            }
        }
    }
}

// ---------------- softmax + head-average + bf16 split ----------------
__device__ __forceinline__ float warpMax(float v) {
    #pragma unroll
    for (int o = 16; o; o >>= 1) v = fmaxf(v, __shfl_xor_sync(0xffffffffu, v, o));
    return v;
}
__device__ __forceinline__ float warpSum(float v) {
    #pragma unroll
    for (int o = 16; o; o >>= 1) v += __shfl_xor_sync(0xffffffffu, v, o);
    return v;
}

__global__ void softmax_avg_kernel(const float* __restrict__ attn,
                                   float* __restrict__ avg)
{
    __shared__ float redM[8], redS[8];
    const int bq = blockIdx.x;
    const int b = bq >> 11;          // SEQ = 2048
    const int q = bq & 2047;
    const int tid = threadIdx.x, lane = tid & 31, wid = tid >> 5;

    float4 a0 = make_float4(0.f, 0.f, 0.f, 0.f);
    float4 a1 = make_float4(0.f, 0.f, 0.f, 0.f);

    // prefetch head 0
    const size_t row0 = ((size_t)(b * NH) * SEQ + q) * SEQ;
    float4 c0 = ((const float4*)(attn + row0))[tid];
    float4 c1 = ((const float4*)(attn + row0))[tid + 256];

    for (int h = 0; h < NH; h++) {
        const size_t rowoff = ((size_t)(b * NH + h) * SEQ + q) * SEQ;
        float4 n0, n1;
        if (h + 1 < NH) {
            const size_t nxt = rowoff + (size_t)SEQ * SEQ;
            n0 = ((const float4*)(attn + nxt))[tid];
            n1 = ((const float4*)(attn + nxt))[tid + 256];
        }

        // ---- max phase (1 barrier) ----
        float mx = fmaxf(fmaxf(fmaxf(c0.x, c0.y), fmaxf(c0.z, c0.w)),
                         fmaxf(fmaxf(c1.x, c1.y), fmaxf(c1.z, c1.w)));
        mx = warpMax(mx);
        if (lane == 0) redM[wid] = mx;
        __syncthreads();
        float rowMax = redM[0];
        #pragma unroll
        for (int i = 1; i < 8; i++) rowMax = fmaxf(rowMax, redM[i]);

        // ---- exp + sum phase (1 barrier) ----
        c0.x = __expf(c0.x - rowMax); c0.y = __expf(c0.y - rowMax);
        c0.z = __expf(c0.z - rowMax); c0.w = __expf(c0.w - rowMax);
        c1.x = __expf(c1.x - rowMax); c1.y = __expf(c1.y - rowMax);
        c1.z = __expf(c1.z - rowMax); c1.w = __expf(c1.w - rowMax);
        float sv = c0.x + c0.y + c0.z + c0.w + c1.x + c1.y + c1.z + c1.w;
        sv = warpSum(sv);
        if (lane == 0) redS[wid] = sv;
        __syncthreads();
        float rs = redS[0];
        #pragma unroll
        for (int i = 1; i < 8; i++) rs += redS[i];
        const float inv = 1.f / rs;

        c0.x *= inv; c0.y *= inv; c0.z *= inv; c0.w *= inv;
        c1.x *= inv; c1.y *= inv; c1.z *= inv; c1.w *= inv;

        __nv_bfloat162* ph2 = (__nv_bfloat162*)(s_p_hi + rowoff);
        __nv_bfloat162* pl2 = (__nv_bfloat162*)(s_p_lo + rowoff);
        __nv_bfloat162 h0, h1, l0, l1;
        bsplit(c0.x, h0.x, l0.x); bsplit(c0.y, h0.y, l0.y);
        bsplit(c0.z, h1.x, l1.x); bsplit(c0.w, h1.y, l1.y);
        ph2[2*tid] = h0; ph2[2*tid+1] = h1;
        pl2[2*tid] = l0; pl2[2*tid+1] = l1;
        bsplit(c1.x, h0.x, l0.x); bsplit(c1.y, h0.y, l0.y);
        bsplit(c1.z, h1.x, l1.x); bsplit(c1.w, h1.y, l1.y);
        ph2[2*(tid+256)] = h0; ph2[2*(tid+256)+1] = h1;
        pl2[2*(tid+256)] = l0; pl2[2*(tid+256)+1] = l1;

        a0.x += c0.x; a0.y += c0.y; a0.z += c0.z; a0.w += c0.w;
        a1.x += c1.x; a1.y += c1.y; a1.z += c1.z; a1.w += c1.w;

        c0 = n0; c1 = n1;
    }

    const float invH = 1.f / NH;
    a0.x *= invH; a0.y *= invH; a0.z *= invH; a0.w *= invH;
    a1.x *= invH; a1.y *= invH; a1.z *= invH; a1.w *= invH;
    float4* o4 = (float4*)(avg + ((size_t)b * SEQ + q) * SEQ);
    o4[tid]       = a0;
    o4[tid + 256] = a1;
}

// ---------------- launch ----------------
extern "C" void kernel_launch(void* const* d_in, const int* in_sizes, int n_in,
                              void* d_out, int out_size)
{
    const float* query   = (const float*)d_in[0];
    const float* key     = (const float*)d_in[1];
    const float* value   = (const float*)d_in[2];
    const float* q_w     = (const float*)d_in[3];
    const float* q_b     = (const float*)d_in[4];
    const float* k_w     = (const float*)d_in[5];
    const float* k_b     = (const float*)d_in[6];
    const float* v_w     = (const float*)d_in[7];
    const float* v_b     = (const float*)d_in[8];
    const float* ow_mean = (const float*)d_in[9];
    const float* ow_lg   = (const float*)d_in[10];
    const float* eps     = (const float*)d_in[11];

    float* out_main = (float*)d_out;
    float* out_avg  = out_main + (size_t)MROWS * EMB;

    __nv_bfloat16 *xqh,*xql,*xkh,*xkl,*xvh,*xvl,*wqh,*wql,*wkh,*wkl,*wvh,*wvl;
    __nv_bfloat16 *owh,*owl,*qh,*ql,*kh,*kl,*vh,*vl,*pph,*ppl,*ch,*cl;
    float* attn_p;
    cudaGetSymbolAddress((void**)&xqh, s_xq_hi); cudaGetSymbolAddress((void**)&xql, s_xq_lo);
    cudaGetSymbolAddress((void**)&xkh, s_xk_hi); cudaGetSymbolAddress((void**)&xkl, s_xk_lo);
    cudaGetSymbolAddress((void**)&xvh, s_xv_hi); cudaGetSymbolAddress((void**)&xvl, s_xv_lo);
    cudaGetSymbolAddress((void**)&wqh, s_wq_hi); cudaGetSymbolAddress((void**)&wql, s_wq_lo);
    cudaGetSymbolAddress((void**)&wkh, s_wk_hi); cudaGetSymbolAddress((void**)&wkl, s_wk_lo);
    cudaGetSymbolAddress((void**)&wvh, s_wv_hi); cudaGetSymbolAddress((void**)&wvl, s_wv_lo);
    cudaGetSymbolAddress((void**)&owh, s_ow_hi); cudaGetSymbolAddress((void**)&owl, s_ow_lo);
    cudaGetSymbolAddress((void**)&qh,  s_q_hi);  cudaGetSymbolAddress((void**)&ql,  s_q_lo);
    cudaGetSymbolAddress((void**)&kh,  s_k_hi);  cudaGetSymbolAddress((void**)&kl,  s_k_lo);
    cudaGetSymbolAddress((void**)&vh,  s_v_hi);  cudaGetSymbolAddress((void**)&vl,  s_v_lo);
    cudaGetSymbolAddress((void**)&pph, s_p_hi);  cudaGetSymbolAddress((void**)&ppl, s_p_lo);
    cudaGetSymbolAddress((void**)&ch,  s_c_hi);  cudaGetSymbolAddress((void**)&cl,  s_c_lo);
    cudaGetSymbolAddress((void**)&attn_p, g_attn);

    // dynamic smem: mainloop kernels 96 KB; score kernel 80 KB (2 CTAs/SM)
    const int SMEM  = 2 * (2 * 128 * 128 + 2 * 64 * 128);
    const int SMEMS = 2 * 128 * 128 + 3 * 2 * 64 * 128;
    cudaFuncSetAttribute(gemm_qkv,    cudaFuncAttributeMaxDynamicSharedMemorySize, SMEM);
    cudaFuncSetAttribute(gemm_score,  cudaFuncAttributeMaxDynamicSharedMemorySize, SMEMS);
    cudaFuncSetAttribute(gemm_mma<0>, cudaFuncAttributeMaxDynamicSharedMemorySize, SMEM);
    cudaFuncSetAttribute(gemm_mma<3>, cudaFuncAttributeMaxDynamicSharedMemorySize, SMEM);

    // 1. fused split (launch #1), sampled output weight (launch #2)
    const int nx4 = MROWS * EMB / 4, nw4 = EMB * EMB / 4;
    {
        Split6Args a;
        a.src[0]=query; a.src[1]=key; a.src[2]=value;
        a.src[3]=q_w;   a.src[4]=k_w; a.src[5]=v_w;
        a.hi[0]=xqh; a.hi[1]=xkh; a.hi[2]=xvh; a.hi[3]=wqh; a.hi[4]=wkh; a.hi[5]=wvh;
        a.lo[0]=xql; a.lo[1]=xkl; a.lo[2]=xvl; a.lo[3]=wql; a.lo[4]=wkl; a.lo[5]=wvl;
        a.n4[0]=a.n4[1]=a.n4[2]=nx4; a.n4[3]=a.n4[4]=a.n4[5]=nw4;
        split6_kernel<<<dim3((nx4 + 255)/256, 6), 256>>>(a);
        ow_split_kernel<<<(nw4 + 255)/256, 256>>>(ow_mean, ow_lg, eps, nw4);
    }

    // 2. fused Q/K/V projections (launch #3)
    const dim3 gQKV(EMB/64, MROWS/128, 3);
    gemm_qkv<<<gQKV, 256, SMEM>>>(q_b, k_b, v_b);

    // 3. scores = Q K^T, streaming-N (launch #4)
    const dim3 gScore(1, SEQ/128, BH);
    gemm_score<<<gScore, 256, SMEMS>>>(qh, ql, kh, kl, attn_p);

    // 4. softmax + avg + bf16 split of probs (launch #5)
    softmax_avg_kernel<<<BSZ*SEQ, 256>>>(attn_p, out_avg);

    // 5. ctx = P @ V (launch #6 — ncu captures this one)
    const dim3 gCtx(1, SEQ/128, BH);
    gemm_mma<3><<<gCtx, 256, SMEM>>>(pph, ppl, vh, vl, SEQ, SEQ, SEQ,
                                     (size_t)SEQ*SEQ, (size_t)HD*SEQ, 0,
                                     nullptr, 0, ch, cl);

    // 6. out = ctx @ o_w^T  (fp32 out)
    const dim3 gOut(EMB/64, MROWS/128, 1);
    gemm_mma<0><<<gOut, 256, SMEM>>>(ch, cl, owh, owl, EMB, EMB, EMB,
                                     0, 0, 0, out_main, EMB,
                                     nullptr, nullptr);
}